// round 11
// baseline (speedup 1.0000x reference)
#include <cuda_runtime.h>
#include <cstdint>
#include <math.h>

#define HH 128
#define WW 128
#define HWSZ (HH*WW)
#define BB 4
#define CINC 128
#define COUTC 128

typedef unsigned long long ull;

// ---------- packed f32x2 helpers (sm_100+ PTX) ----------
__device__ __forceinline__ ull ffma2(ull a, ull b, ull c) {
    ull d;
    asm("fma.rn.f32x2 %0, %1, %2, %3;" : "=l"(d) : "l"(a), "l"(b), "l"(c));
    return d;
}
__device__ __forceinline__ ull pack2(float x, float y) {
    ull r;
    unsigned xi = __float_as_uint(x), yi = __float_as_uint(y);
    asm("mov.b64 %0, {%1, %2};" : "=l"(r) : "r"(xi), "r"(yi));
    return r;
}
__device__ __forceinline__ void unpack2(ull v, float& x, float& y) {
    unsigned xi, yi;
    asm("mov.b64 {%0, %1}, %2;" : "=r"(xi), "=r"(yi) : "l"(v));
    x = __uint_as_float(xi);
    y = __uint_as_float(yi);
}

// ---------- scratch (no allocations allowed -> __device__ globals) ----------
__device__ float g_f1[BB * COUTC * HWSZ];        // 32 MB
__device__ float g_f2[BB * COUTC * HWSZ];        // 32 MB
__device__ float g_head[BB * 32 * HWSZ];         // 8 MB (27 used, padded to 32)
__device__ float g_w1T[261 * 9 * 128];
__device__ float g_w2T[128 * 9 * 128];
__device__ float g_w3T[128 * 9 * 128];
__device__ float g_w4T[128 * 9 * 32];
__device__ float g_wdT[128 * 9 * 128];
__device__ float g_b4p[32];

// ---------- prep: transpose OIHW weights to [cin][k][cout_pad] ----------
__global__ void transpose_w_kernel(const float* __restrict__ w, float* __restrict__ wT,
                                   int Cout, int Cin, int CoutPad) {
    int i = blockIdx.x * blockDim.x + threadIdx.x;
    int total = Cin * 9 * CoutPad;
    if (i >= total) return;
    int co = i % CoutPad;
    int t = i / CoutPad;
    int k = t % 9;
    int ci = t / 9;
    wT[i] = (co < Cout) ? w[(co * Cin + ci) * 9 + k] : 0.f;
}

__global__ void pad_bias_kernel(const float* __restrict__ b, float* __restrict__ bp,
                                int n, int np) {
    int i = threadIdx.x;
    if (i < np) bp[i] = (i < n) ? b[i] : 0.f;
}

// ---------- conv3x3 (SAME, stride 1), f32x2 register tile ----------
// block tile: 8 rows x 32 cols x 32 couts; thread: 4 px (W) x 8 couts.
template <bool LRELU>
__global__ __launch_bounds__(256, 2)
void conv3x3_kernel(const float* __restrict__ in, const float* __restrict__ wT,
                    const float* __restrict__ bias, float* __restrict__ out,
                    int Cin, int CoutTot) {
    __shared__ __align__(16) float xs[8][10][35];   // rows y0-1..y0+8, cols x0-1..x0+32 (34 used)
    __shared__ __align__(16) float ws[8][9][32];    // [cin_local][k][cout_local]

    const int tid = threadIdx.x;
    const int tx4 = (tid & 7) * 4;
    const int ty  = (tid >> 3) & 7;
    const int cz  = tid >> 6;            // 0..3 -> couts cz*8 .. cz*8+7
    const int x0 = blockIdx.x * 32;
    const int y0 = blockIdx.y * 8;
    const int ncg = CoutTot >> 5;
    const int b  = blockIdx.z / ncg;
    const int cg = blockIdx.z - b * ncg;
    const int cbase = cg * 32;

    ull acc[4][4];
    #pragma unroll
    for (int p = 0; p < 4; ++p)
        #pragma unroll
        for (int px = 0; px < 4; ++px) acc[p][px] = 0ull;

    const int nch = (Cin + 7) >> 3;
    for (int ch = 0; ch < nch; ++ch) {
        const int c0 = ch * 8;
        // stage input tile (zeros outside image / channel range)
        for (int i = tid; i < 8 * 10 * 34; i += 256) {
            int c = i / 340;
            int rm = i - c * 340;
            int r = rm / 34;
            int col = rm - r * 34;
            int ci = c0 + c;
            int gy = y0 - 1 + r;
            int gx = x0 - 1 + col;
            float v = 0.f;
            if (ci < Cin && (unsigned)gy < (unsigned)HH && (unsigned)gx < (unsigned)WW)
                v = in[((size_t)(b * Cin + ci) * HH + gy) * WW + gx];
            xs[c][r][col] = v;
        }
        // stage weights (coalesced from transposed layout)
        for (int i = tid; i < 8 * 9 * 32; i += 256) {
            int c = i / 288;
            int rm = i - c * 288;
            int k = rm >> 5;
            int co = rm & 31;
            int ci = c0 + c;
            ws[c][k][co] = (ci < Cin) ? wT[(size_t)(ci * 9 + k) * CoutTot + cbase + co] : 0.f;
        }
        __syncthreads();

        #pragma unroll 1
        for (int c = 0; c < 8; ++c) {
            ull pin[3][6];
            #pragma unroll
            for (int r = 0; r < 3; ++r)
                #pragma unroll
                for (int j = 0; j < 6; ++j) {
                    float v = xs[c][ty + r][tx4 + j];
                    pin[r][j] = pack2(v, v);
                }
            #pragma unroll
            for (int k = 0; k < 9; ++k) {
                const int r = k / 3, s = k - 3 * (k / 3);
                const ull* wp = (const ull*)&ws[c][k][cz * 8];
                ull w0 = wp[0], w1 = wp[1], w2 = wp[2], w3 = wp[3];
                #pragma unroll
                for (int px = 0; px < 4; ++px) {
                    ull v = pin[r][s + px];
                    acc[0][px] = ffma2(v, w0, acc[0][px]);
                    acc[1][px] = ffma2(v, w1, acc[1][px]);
                    acc[2][px] = ffma2(v, w2, acc[2][px]);
                    acc[3][px] = ffma2(v, w3, acc[3][px]);
                }
            }
        }
        __syncthreads();
    }

    // epilogue: bias (+optional leaky relu), vectorized stores
    const int y = y0 + ty;
    #pragma unroll
    for (int p = 0; p < 4; ++p) {
        int co = cbase + cz * 8 + 2 * p;
        float blo = bias[co], bhi = bias[co + 1];
        float4 vlo, vhi;
        float a, bb2;
        unpack2(acc[p][0], a, bb2); vlo.x = a + blo; vhi.x = bb2 + bhi;
        unpack2(acc[p][1], a, bb2); vlo.y = a + blo; vhi.y = bb2 + bhi;
        unpack2(acc[p][2], a, bb2); vlo.z = a + blo; vhi.z = bb2 + bhi;
        unpack2(acc[p][3], a, bb2); vlo.w = a + blo; vhi.w = bb2 + bhi;
        if (LRELU) {
            vlo.x = vlo.x >= 0.f ? vlo.x : 0.1f * vlo.x;
            vlo.y = vlo.y >= 0.f ? vlo.y : 0.1f * vlo.y;
            vlo.z = vlo.z >= 0.f ? vlo.z : 0.1f * vlo.z;
            vlo.w = vlo.w >= 0.f ? vlo.w : 0.1f * vlo.w;
            vhi.x = vhi.x >= 0.f ? vhi.x : 0.1f * vhi.x;
            vhi.y = vhi.y >= 0.f ? vhi.y : 0.1f * vhi.y;
            vhi.z = vhi.z >= 0.f ? vhi.z : 0.1f * vhi.z;
            vhi.w = vhi.w >= 0.f ? vhi.w : 0.1f * vhi.w;
        }
        float* o0 = out + ((size_t)(b * CoutTot + co) * HH + y) * WW + x0 + tx4;
        *(float4*)o0 = vlo;
        *(float4*)(o0 + HWSZ) = vhi;
    }
}

// ---------- modulated deformable conv ----------
// block tile: 16 (W) x 4 (H) pixels x all 128 couts; thread: 2 px x 16 couts.
__global__ __launch_bounds__(256, 2)
void deform_kernel(const float* __restrict__ x, const float* __restrict__ head,
                   const float* __restrict__ flow, const float* __restrict__ wdT,
                   const float* __restrict__ bias, float* __restrict__ out) {
    __shared__ __align__(16) float4 sw[576];      // [k*64+p] bilinear weights (mask folded)
    __shared__ __align__(16) int4  sidx[576];     // [k*64+p] clamped corner offsets
    __shared__ __align__(16) float wsm[4 * 9 * 128];  // [c][k][co]
    __shared__ __align__(16) float ssm[4 * 9 * 64];   // [c][k][p]

    const int tid = threadIdx.x;
    const int b = blockIdx.z;
    const int x0 = blockIdx.x * 16;
    const int y0 = blockIdx.y * 4;

    // phase 0: per-(tap, pixel) sampling parameters
    for (int e = tid; e < 576; e += 256) {
        int k = e >> 6;
        int p = e & 63;
        int y = y0 + (p >> 4);
        int xx = x0 + (p & 15);
        int pix = y * WW + xx;
        const float* hb = head + (size_t)b * 32 * HWSZ + pix;
        float dyr = hb[(2 * k) * HWSZ];
        float dxr = hb[(2 * k + 1) * HWSZ];
        float mr  = hb[(18 + k) * HWSZ];
        const float* fb = flow + (size_t)b * 2 * HWSZ + pix;
        float fx = fb[0];
        float fy = fb[HWSZ];
        // base = p - 1 + tap; offset = 3*tanh(head) + flipped flow
        float py = (float)(y - 1 + k / 3) + 3.0f * tanhf(dyr) + fy;
        float px = (float)(xx - 1 + (k - 3 * (k / 3))) + 3.0f * tanhf(dxr) + fx;
        float m = 1.0f / (1.0f + __expf(-mr));  // sigmoid(mask)
        float fy0 = floorf(py), fx0 = floorf(px);
        float ay = py - fy0, ax = px - fx0;
        int iy0 = (int)fy0, ix0 = (int)fx0;
        int iy1 = iy0 + 1, ix1 = ix0 + 1;
        float vy0 = (iy0 >= 0 && iy0 < HH) ? m : 0.f;
        float vy1 = (iy1 >= 0 && iy1 < HH) ? m : 0.f;
        float vx0 = (ix0 >= 0 && ix0 < WW) ? 1.f : 0.f;
        float vx1 = (ix1 >= 0 && ix1 < WW) ? 1.f : 0.f;
        float w00 = (1.f - ay) * (1.f - ax) * vy0 * vx0;
        float w01 = (1.f - ay) * ax * vy0 * vx1;
        float w10 = ay * (1.f - ax) * vy1 * vx0;
        float w11 = ay * ax * vy1 * vx1;
        int cy0 = min(max(iy0, 0), HH - 1), cy1 = min(max(iy1, 0), HH - 1);
        int cx0 = min(max(ix0, 0), WW - 1), cx1 = min(max(ix1, 0), WW - 1);
        sw[e] = make_float4(w00, w01, w10, w11);
        sidx[e] = make_int4(cy0 * WW + cx0, cy0 * WW + cx1, cy1 * WW + cx0, cy1 * WW + cx1);
    }

    const int g = tid >> 5;    // 0..7 -> couts g*16..g*16+15
    const int ph = tid & 31;   // pixel pair (2*ph, 2*ph+1)

    ull acc[2][8];
    #pragma unroll
    for (int q = 0; q < 8; ++q) {
        float b0 = bias[g * 16 + 2 * q];
        float b1 = bias[g * 16 + 2 * q + 1];
        acc[0][q] = pack2(b0, b1);
        acc[1][q] = pack2(b0, b1);
    }

    for (int c0 = 0; c0 < CINC; c0 += 4) {
        __syncthreads();  // prev GEMM done reading smem (and phase-0 visible on 1st iter)
        // stage chunk weights (contiguous in wdT)
        const float4* wsrc = (const float4*)(wdT + (size_t)c0 * 9 * 128);
        for (int i = tid; i < (4 * 9 * 128) / 4; i += 256)
            ((float4*)wsm)[i] = wsrc[i];
        // bilinear sampling for 4 channels x 9 taps x 64 px
        for (int e2 = tid; e2 < 4 * 576; e2 += 256) {
            int c = e2 / 576;
            int e = e2 - c * 576;
            float4 wv = sw[e];
            int4 iv = sidx[e];
            const float* xp = x + (size_t)(b * CINC + c0 + c) * HWSZ;
            float v = wv.x * __ldg(xp + iv.x) + wv.y * __ldg(xp + iv.y)
                    + wv.z * __ldg(xp + iv.z) + wv.w * __ldg(xp + iv.w);
            ssm[c * 576 + e] = v;
        }
        __syncthreads();

        // register GEMM: 36 (c,k) steps x 16 couts x 2 px
        #pragma unroll 4
        for (int ck = 0; ck < 36; ++ck) {
            float2 sv = *(const float2*)&ssm[ck * 64 + 2 * ph];
            ull s0 = pack2(sv.x, sv.x);
            ull s1 = pack2(sv.y, sv.y);
            const float4* wrow = (const float4*)&wsm[ck * 128 + g * 16];
            #pragma unroll
            for (int q4 = 0; q4 < 4; ++q4) {
                float4 wv = wrow[q4];
                ull w01 = pack2(wv.x, wv.y);
                ull w23 = pack2(wv.z, wv.w);
                acc[0][2 * q4]     = ffma2(s0, w01, acc[0][2 * q4]);
                acc[0][2 * q4 + 1] = ffma2(s0, w23, acc[0][2 * q4 + 1]);
                acc[1][2 * q4]     = ffma2(s1, w01, acc[1][2 * q4]);
                acc[1][2 * q4 + 1] = ffma2(s1, w23, acc[1][2 * q4 + 1]);
            }
        }
    }

    // epilogue: 16 couts x 2 adjacent px per thread
    int p0 = 2 * ph;
    int yy = y0 + (p0 >> 4);
    int xx = x0 + (p0 & 15);
    #pragma unroll
    for (int q = 0; q < 8; ++q) {
        int co = g * 16 + 2 * q;
        float a0, a1, c0v, c1v;
        unpack2(acc[0][q], a0, a1);
        unpack2(acc[1][q], c0v, c1v);
        float* o = out + ((size_t)(b * COUTC + co) * HH + yy) * WW + xx;
        *(float2*)o = make_float2(a0, c0v);
        *(float2*)(o + HWSZ) = make_float2(a1, c1v);
    }
}

// ---------- launcher ----------
extern "C" void kernel_launch(void* const* d_in, const int* in_sizes, int n_in,
                              void* d_out, int out_size) {
    const float* x    = (const float*)d_in[0];
    const float* cond = (const float*)d_in[1];
    const float* flow = (const float*)d_in[2];
    const float* w1 = (const float*)d_in[3];
    const float* b1 = (const float*)d_in[4];
    const float* w2 = (const float*)d_in[5];
    const float* b2 = (const float*)d_in[6];
    const float* w3 = (const float*)d_in[7];
    const float* b3 = (const float*)d_in[8];
    const float* w4 = (const float*)d_in[9];
    const float* b4 = (const float*)d_in[10];
    const float* wd = (const float*)d_in[11];
    const float* bd = (const float*)d_in[12];
    float* out = (float*)d_out;

    float *f1, *f2, *headp, *w1T, *w2T, *w3T, *w4T, *wdT, *b4p;
    cudaGetSymbolAddress((void**)&f1,   g_f1);
    cudaGetSymbolAddress((void**)&f2,   g_f2);
    cudaGetSymbolAddress((void**)&headp, g_head);
    cudaGetSymbolAddress((void**)&w1T,  g_w1T);
    cudaGetSymbolAddress((void**)&w2T,  g_w2T);
    cudaGetSymbolAddress((void**)&w3T,  g_w3T);
    cudaGetSymbolAddress((void**)&w4T,  g_w4T);
    cudaGetSymbolAddress((void**)&wdT,  g_wdT);
    cudaGetSymbolAddress((void**)&b4p,  g_b4p);

    const int CCOND = 261;

    transpose_w_kernel<<<(CCOND * 9 * 128 + 255) / 256, 256>>>(w1, w1T, 128, CCOND, 128);
    transpose_w_kernel<<<(128 * 9 * 128 + 255) / 256, 256>>>(w2, w2T, 128, 128, 128);
    transpose_w_kernel<<<(128 * 9 * 128 + 255) / 256, 256>>>(w3, w3T, 128, 128, 128);
    transpose_w_kernel<<<(128 * 9 * 32 + 255) / 256, 256>>>(w4, w4T, 27, 128, 32);
    transpose_w_kernel<<<(128 * 9 * 128 + 255) / 256, 256>>>(wd, wdT, 128, 128, 128);
    pad_bias_kernel<<<1, 32>>>(b4, b4p, 27, 32);

    dim3 g128(4, 16, 4 * 4);   // Wtiles, Htiles, B * cout_groups
    conv3x3_kernel<true><<<g128, 256>>>(cond, w1T, b1, f1, CCOND, 128);
    conv3x3_kernel<true><<<g128, 256>>>(f1, w2T, b2, f2, 128, 128);
    conv3x3_kernel<true><<<g128, 256>>>(f2, w3T, b3, f1, 128, 128);

    dim3 ghead(4, 16, 4 * 1);
    conv3x3_kernel<false><<<ghead, 256>>>(f1, w4T, b4p, headp, 128, 32);

    dim3 gdef(8, 32, 4);       // Wtiles(16), Htiles(4), B
    deform_kernel<<<gdef, 256>>>(x, headp, flow, wdT, bd, out);
}

// round 12
// speedup vs baseline: 1.0084x; 1.0084x over previous
#include <cuda_runtime.h>
#include <cstdint>
#include <math.h>

#define HH 128
#define WW 128
#define HWSZ (HH*WW)
#define BB 4
#define CINC 128
#define COUTC 128

typedef unsigned long long ull;

// ---------- packed f32x2 helpers (sm_100+ PTX) ----------
__device__ __forceinline__ ull ffma2(ull a, ull b, ull c) {
    ull d;
    asm("fma.rn.f32x2 %0, %1, %2, %3;" : "=l"(d) : "l"(a), "l"(b), "l"(c));
    return d;
}
__device__ __forceinline__ ull pack2(float x, float y) {
    ull r;
    unsigned xi = __float_as_uint(x), yi = __float_as_uint(y);
    asm("mov.b64 %0, {%1, %2};" : "=l"(r) : "r"(xi), "r"(yi));
    return r;
}
__device__ __forceinline__ void unpack2(ull v, float& x, float& y) {
    unsigned xi, yi;
    asm("mov.b64 {%0, %1}, %2;" : "=r"(xi), "=r"(yi) : "l"(v));
    x = __uint_as_float(xi);
    y = __uint_as_float(yi);
}

// ---------- scratch (no allocations allowed -> __device__ globals) ----------
__device__ float g_f1[BB * COUTC * HWSZ];        // 32 MB
__device__ float g_f2[BB * COUTC * HWSZ];        // 32 MB
__device__ float g_xt[BB * CINC * HWSZ];         // 32 MB : x in NHWC [b][pix][c]
__device__ float g_head[BB * 32 * HWSZ];         // 8 MB (27 used, padded to 32)
__device__ float g_w1T[261 * 9 * 128];
__device__ float g_w2T[128 * 9 * 128];
__device__ float g_w3T[128 * 9 * 128];
__device__ float g_w4T[128 * 9 * 32];
__device__ float g_wdT[128 * 9 * 128];
__device__ float g_b4p[32];

// ---------- fused prep: NHWC transpose of x + all weight transposes + bias pad ----
// region A (blocks [0, 8192)): x NCHW -> NHWC via 32x32 smem tiles
// region B (rest): OIHW -> [cin][k][cout_pad] for w1..w4, wd; pad b4.
#define NHWC_BLOCKS 8192
#define N1T (261*9*128)
#define N2T (128*9*128)
#define N4T (128*9*32)
#define PREP_TOTAL (N1T + 3*N2T + N4T + 32)
#define PREP_BLOCKS ((PREP_TOTAL + 255) / 256)

__device__ __forceinline__ void wtrans_one(long i, const float* __restrict__ w,
                                           float* __restrict__ wT,
                                           int Cout, int Cin, int CoutPad) {
    int co = (int)(i % CoutPad);
    long t = i / CoutPad;
    int k = (int)(t % 9);
    int ci = (int)(t / 9);
    wT[i] = (co < Cout) ? w[((size_t)co * Cin + ci) * 9 + k] : 0.f;
}

__global__ void prep_kernel(const float* __restrict__ x, float* __restrict__ xt,
                            const float* __restrict__ w1, const float* __restrict__ w2,
                            const float* __restrict__ w3, const float* __restrict__ w4,
                            const float* __restrict__ wd, const float* __restrict__ b4,
                            float* __restrict__ w1T, float* __restrict__ w2T,
                            float* __restrict__ w3T, float* __restrict__ w4T,
                            float* __restrict__ wdT, float* __restrict__ b4p) {
    if (blockIdx.x < NHWC_BLOCKS) {
        __shared__ float t[32][33];
        int bid = blockIdx.x;
        int pT = bid & 511;
        int cT = (bid >> 9) & 3;
        int b  = bid >> 11;
        int tx = threadIdx.x & 31;
        int ty = threadIdx.x >> 5;           // 0..7
        int p0 = pT * 32, c0 = cT * 32;
        const float* ib = x + (size_t)b * CINC * HWSZ;
        float* ob = xt + (size_t)b * HWSZ * CINC;
        #pragma unroll
        for (int i = 0; i < 4; ++i)
            t[ty + 8 * i][tx] = ib[(size_t)(c0 + ty + 8 * i) * HWSZ + p0 + tx];
        __syncthreads();
        #pragma unroll
        for (int i = 0; i < 4; ++i)
            ob[(size_t)(p0 + ty + 8 * i) * CINC + c0 + tx] = t[tx][ty + 8 * i];
    } else {
        long i = (long)(blockIdx.x - NHWC_BLOCKS) * 256 + threadIdx.x;
        if (i >= PREP_TOTAL) return;
        if (i < N1T) { wtrans_one(i, w1, w1T, 128, 261, 128); return; }
        i -= N1T;
        if (i < N2T) { wtrans_one(i, w2, w2T, 128, 128, 128); return; }
        i -= N2T;
        if (i < N2T) { wtrans_one(i, w3, w3T, 128, 128, 128); return; }
        i -= N2T;
        if (i < N2T) { wtrans_one(i, wd, wdT, 128, 128, 128); return; }
        i -= N2T;
        if (i < N4T) { wtrans_one(i, w4, w4T, 27, 128, 32); return; }
        i -= N4T;
        b4p[i] = (i < 27) ? b4[i] : 0.f;
    }
}

// ---------- conv3x3 (SAME, stride 1), f32x2 register tile, ping-pong smem ----------
// block tile: 8 rows x 32 cols x 32 couts; thread: 4 px (W) x 8 couts.
template <bool LRELU>
__global__ __launch_bounds__(256, 2)
void conv3x3_kernel(const float* __restrict__ in, const float* __restrict__ wT,
                    const float* __restrict__ bias, float* __restrict__ out,
                    int Cin, int CoutTot) {
    __shared__ __align__(16) float xs[2][8][10][35];
    __shared__ __align__(16) float ws[2][8][9][32];

    const int tid = threadIdx.x;
    const int tx4 = (tid & 7) * 4;
    const int ty  = (tid >> 3) & 7;
    const int cz  = tid >> 6;
    const int x0 = blockIdx.x * 32;
    const int y0 = blockIdx.y * 8;
    const int ncg = CoutTot >> 5;
    const int b  = blockIdx.z / ncg;
    const int cg = blockIdx.z - b * ncg;
    const int cbase = cg * 32;

    ull acc[4][4];
    #pragma unroll
    for (int p = 0; p < 4; ++p)
        #pragma unroll
        for (int px = 0; px < 4; ++px) acc[p][px] = 0ull;

    const int nch = (Cin + 7) >> 3;

    auto stage = [&](int ch, int buf) {
        const int c0 = ch * 8;
        for (int i = tid; i < 8 * 10 * 34; i += 256) {
            int c = i / 340;
            int rm = i - c * 340;
            int r = rm / 34;
            int col = rm - r * 34;
            int ci = c0 + c;
            int gy = y0 - 1 + r;
            int gx = x0 - 1 + col;
            float v = 0.f;
            if (ci < Cin && (unsigned)gy < (unsigned)HH && (unsigned)gx < (unsigned)WW)
                v = in[((size_t)(b * Cin + ci) * HH + gy) * WW + gx];
            xs[buf][c][r][col] = v;
        }
        for (int i = tid; i < 8 * 9 * 32; i += 256) {
            int c = i / 288;
            int rm = i - c * 288;
            int k = rm >> 5;
            int co = rm & 31;
            int ci = c0 + c;
            ws[buf][c][k][co] = (ci < Cin) ? wT[(size_t)(ci * 9 + k) * CoutTot + cbase + co] : 0.f;
        }
    };

    stage(0, 0);
    __syncthreads();

    for (int ch = 0; ch < nch; ++ch) {
        const int cur = ch & 1;
        if (ch + 1 < nch) stage(ch + 1, cur ^ 1);   // overlaps other warps' compute

        #pragma unroll 1
        for (int c = 0; c < 8; ++c) {
            ull pin[3][6];
            #pragma unroll
            for (int r = 0; r < 3; ++r)
                #pragma unroll
                for (int j = 0; j < 6; ++j) {
                    float v = xs[cur][c][ty + r][tx4 + j];
                    pin[r][j] = pack2(v, v);
                }
            #pragma unroll
            for (int k = 0; k < 9; ++k) {
                const int r = k / 3, s = k - 3 * (k / 3);
                const ull* wp = (const ull*)&ws[cur][c][k][cz * 8];
                ull w0 = wp[0], w1 = wp[1], w2 = wp[2], w3 = wp[3];
                #pragma unroll
                for (int px = 0; px < 4; ++px) {
                    ull v = pin[r][s + px];
                    acc[0][px] = ffma2(v, w0, acc[0][px]);
                    acc[1][px] = ffma2(v, w1, acc[1][px]);
                    acc[2][px] = ffma2(v, w2, acc[2][px]);
                    acc[3][px] = ffma2(v, w3, acc[3][px]);
                }
            }
        }
        __syncthreads();
    }

    const int y = y0 + ty;
    #pragma unroll
    for (int p = 0; p < 4; ++p) {
        int co = cbase + cz * 8 + 2 * p;
        float blo = bias[co], bhi = bias[co + 1];
        float4 vlo, vhi;
        float a, bb2;
        unpack2(acc[p][0], a, bb2); vlo.x = a + blo; vhi.x = bb2 + bhi;
        unpack2(acc[p][1], a, bb2); vlo.y = a + blo; vhi.y = bb2 + bhi;
        unpack2(acc[p][2], a, bb2); vlo.z = a + blo; vhi.z = bb2 + bhi;
        unpack2(acc[p][3], a, bb2); vlo.w = a + blo; vhi.w = bb2 + bhi;
        if (LRELU) {
            vlo.x = vlo.x >= 0.f ? vlo.x : 0.1f * vlo.x;
            vlo.y = vlo.y >= 0.f ? vlo.y : 0.1f * vlo.y;
            vlo.z = vlo.z >= 0.f ? vlo.z : 0.1f * vlo.z;
            vlo.w = vlo.w >= 0.f ? vlo.w : 0.1f * vlo.w;
            vhi.x = vhi.x >= 0.f ? vhi.x : 0.1f * vhi.x;
            vhi.y = vhi.y >= 0.f ? vhi.y : 0.1f * vhi.y;
            vhi.z = vhi.z >= 0.f ? vhi.z : 0.1f * vhi.z;
            vhi.w = vhi.w >= 0.f ? vhi.w : 0.1f * vhi.w;
        }
        float* o0 = out + ((size_t)(b * CoutTot + co) * HH + y) * WW + x0 + tx4;
        *(float4*)o0 = vlo;
        *(float4*)(o0 + HWSZ) = vhi;
    }
}

// ---------- modulated deformable conv, NHWC gather + ping-pong ----------
// block tile: 16 (W) x 4 (H) pixels x all 128 couts; thread: 2 px x 16 couts.
// dynamic smem layout:
//   sw    float4[576]            9216 B
//   sidx  int4[576]              9216 B
//   wsm   float[2][4*9*128]     36864 B
//   ssm   float4[2][576]        18432 B   ([k*64+p] -> 4 channels)
#define DEF_SMEM (9216 + 9216 + 36864 + 18432)

__global__ __launch_bounds__(256, 2)
void deform_kernel(const float* __restrict__ xt, const float* __restrict__ head,
                   const float* __restrict__ flow, const float* __restrict__ wdT,
                   const float* __restrict__ bias, float* __restrict__ out) {
    extern __shared__ char dsm_raw[];
    float4* sw  = (float4*)dsm_raw;
    int4*  sidx = (int4*)(dsm_raw + 9216);
    float* wsm  = (float*)(dsm_raw + 18432);
    float4* ssm = (float4*)(dsm_raw + 18432 + 36864);

    const int tid = threadIdx.x;
    const int b = blockIdx.z;
    const int x0 = blockIdx.x * 16;
    const int y0 = blockIdx.y * 4;

    // phase 0: per-(tap, pixel) sampling parameters
    for (int e = tid; e < 576; e += 256) {
        int k = e >> 6;
        int p = e & 63;
        int y = y0 + (p >> 4);
        int xx = x0 + (p & 15);
        int pix = y * WW + xx;
        const float* hb = head + (size_t)b * 32 * HWSZ + pix;
        float dyr = hb[(2 * k) * HWSZ];
        float dxr = hb[(2 * k + 1) * HWSZ];
        float mr  = hb[(18 + k) * HWSZ];
        const float* fb = flow + (size_t)b * 2 * HWSZ + pix;
        float fx = fb[0];
        float fy = fb[HWSZ];
        float py = (float)(y - 1 + k / 3) + 3.0f * tanhf(dyr) + fy;
        float px = (float)(xx - 1 + (k - 3 * (k / 3))) + 3.0f * tanhf(dxr) + fx;
        float m = 1.0f / (1.0f + __expf(-mr));
        float fy0 = floorf(py), fx0 = floorf(px);
        float ay = py - fy0, ax = px - fx0;
        int iy0 = (int)fy0, ix0 = (int)fx0;
        int iy1 = iy0 + 1, ix1 = ix0 + 1;
        float vy0 = (iy0 >= 0 && iy0 < HH) ? m : 0.f;
        float vy1 = (iy1 >= 0 && iy1 < HH) ? m : 0.f;
        float vx0 = (ix0 >= 0 && ix0 < WW) ? 1.f : 0.f;
        float vx1 = (ix1 >= 0 && ix1 < WW) ? 1.f : 0.f;
        float w00 = (1.f - ay) * (1.f - ax) * vy0 * vx0;
        float w01 = (1.f - ay) * ax * vy0 * vx1;
        float w10 = ay * (1.f - ax) * vy1 * vx0;
        float w11 = ay * ax * vy1 * vx1;
        int cy0 = min(max(iy0, 0), HH - 1), cy1 = min(max(iy1, 0), HH - 1);
        int cx0 = min(max(ix0, 0), WW - 1), cx1 = min(max(ix1, 0), WW - 1);
        sw[e] = make_float4(w00, w01, w10, w11);
        sidx[e] = make_int4(cy0 * WW + cx0, cy0 * WW + cx1, cy1 * WW + cx0, cy1 * WW + cx1);
    }

    const int g = tid >> 5;    // 0..7 -> couts g*16..g*16+15
    const int ph = tid & 31;   // pixels ph and ph+32

    ull acc[2][8];
    #pragma unroll
    for (int q = 0; q < 8; ++q) {
        float b0 = bias[g * 16 + 2 * q];
        float b1 = bias[g * 16 + 2 * q + 1];
        acc[0][q] = pack2(b0, b1);
        acc[1][q] = pack2(b0, b1);
    }

    const float* xb = xt + (size_t)b * HWSZ * CINC;   // NHWC [pix][c]

    auto stage = [&](int c0, int buf) {
        // chunk weights: 4 cin x 9 k x 128 co, contiguous in wdT
        const float4* wsrc = (const float4*)(wdT + (size_t)c0 * 9 * 128);
        float4* wdst = (float4*)(wsm + buf * 4608);
        for (int i = tid; i < 1152; i += 256) wdst[i] = wsrc[i];
        // bilinear gather: per (k,p), one LDG.128 per corner covers 4 channels
        float4* sd = ssm + buf * 576;
        for (int e = tid; e < 576; e += 256) {
            float4 wv = sw[e];
            int4 iv = sidx[e];
            float4 v00 = __ldg((const float4*)(xb + (size_t)iv.x * CINC + c0));
            float4 v01 = __ldg((const float4*)(xb + (size_t)iv.y * CINC + c0));
            float4 v10 = __ldg((const float4*)(xb + (size_t)iv.z * CINC + c0));
            float4 v11 = __ldg((const float4*)(xb + (size_t)iv.w * CINC + c0));
            float4 r;
            r.x = wv.x * v00.x + wv.y * v01.x + wv.z * v10.x + wv.w * v11.x;
            r.y = wv.x * v00.y + wv.y * v01.y + wv.z * v10.y + wv.w * v11.y;
            r.z = wv.x * v00.z + wv.y * v01.z + wv.z * v10.z + wv.w * v11.z;
            r.w = wv.x * v00.w + wv.y * v01.w + wv.z * v10.w + wv.w * v11.w;
            sd[e] = r;
        }
    };

    __syncthreads();          // sw/sidx visible
    stage(0, 0);
    __syncthreads();

    for (int ci = 0; ci < 32; ++ci) {
        const int cur = ci & 1;
        if (ci + 1 < 32) stage((ci + 1) * 4, cur ^ 1);

        const float* wsmb = wsm + cur * 4608;
        const float4* ssmb = ssm + cur * 576;
        #pragma unroll
        for (int k = 0; k < 9; ++k) {
            float4 s0 = ssmb[k * 64 + ph];          // px0 = ph (stride 16B: conflict-free)
            float4 s1 = ssmb[k * 64 + ph + 32];     // px1 = ph+32
            #pragma unroll
            for (int c = 0; c < 4; ++c) {
                float f0 = (&s0.x)[c];
                float f1 = (&s1.x)[c];
                ull a0 = pack2(f0, f0);
                ull a1 = pack2(f1, f1);
                const float4* wrow = (const float4*)(wsmb + (c * 9 + k) * 128 + g * 16);
                #pragma unroll
                for (int q4 = 0; q4 < 4; ++q4) {
                    float4 wv = wrow[q4];
                    ull w01 = pack2(wv.x, wv.y);
                    ull w23 = pack2(wv.z, wv.w);
                    acc[0][2 * q4]     = ffma2(a0, w01, acc[0][2 * q4]);
                    acc[0][2 * q4 + 1] = ffma2(a0, w23, acc[0][2 * q4 + 1]);
                    acc[1][2 * q4]     = ffma2(a1, w01, acc[1][2 * q4]);
                    acc[1][2 * q4 + 1] = ffma2(a1, w23, acc[1][2 * q4 + 1]);
                }
            }
        }
        __syncthreads();
    }

    // epilogue: 16 couts x 2 px (ph, ph+32 -> rows y, y+2)
    int yy0 = y0 + (ph >> 4);
    int xx0 = x0 + (ph & 15);
    #pragma unroll
    for (int q = 0; q < 8; ++q) {
        int co = g * 16 + 2 * q;
        float a0, a1, c0v, c1v;
        unpack2(acc[0][q], a0, a1);
        unpack2(acc[1][q], c0v, c1v);
        float* o = out + ((size_t)(b * COUTC + co) * HH + yy0) * WW + xx0;
        o[0] = a0;
        o[HWSZ] = a1;
        o[2 * WW] = c0v;
        o[HWSZ + 2 * WW] = c1v;
    }
}

// ---------- launcher ----------
extern "C" void kernel_launch(void* const* d_in, const int* in_sizes, int n_in,
                              void* d_out, int out_size) {
    const float* x    = (const float*)d_in[0];
    const float* cond = (const float*)d_in[1];
    const float* flow = (const float*)d_in[2];
    const float* w1 = (const float*)d_in[3];
    const float* b1 = (const float*)d_in[4];
    const float* w2 = (const float*)d_in[5];
    const float* b2 = (const float*)d_in[6];
    const float* w3 = (const float*)d_in[7];
    const float* b3 = (const float*)d_in[8];
    const float* w4 = (const float*)d_in[9];
    const float* b4 = (const float*)d_in[10];
    const float* wd = (const float*)d_in[11];
    const float* bd = (const float*)d_in[12];
    float* out = (float*)d_out;

    float *f1, *f2, *xtp, *headp, *w1T, *w2T, *w3T, *w4T, *wdT, *b4p;
    cudaGetSymbolAddress((void**)&f1,    g_f1);
    cudaGetSymbolAddress((void**)&f2,    g_f2);
    cudaGetSymbolAddress((void**)&xtp,   g_xt);
    cudaGetSymbolAddress((void**)&headp, g_head);
    cudaGetSymbolAddress((void**)&w1T,   g_w1T);
    cudaGetSymbolAddress((void**)&w2T,   g_w2T);
    cudaGetSymbolAddress((void**)&w3T,   g_w3T);
    cudaGetSymbolAddress((void**)&w4T,   g_w4T);
    cudaGetSymbolAddress((void**)&wdT,   g_wdT);
    cudaGetSymbolAddress((void**)&b4p,   g_b4p);

    cudaFuncSetAttribute(deform_kernel, cudaFuncAttributeMaxDynamicSharedMemorySize, DEF_SMEM);

    // launch 0: fused prep (NHWC transpose + all weight prep)
    prep_kernel<<<NHWC_BLOCKS + PREP_BLOCKS, 256>>>(
        x, xtp, w1, w2, w3, w4, wd, b4, w1T, w2T, w3T, w4T, wdT, b4p);

    dim3 g128(4, 16, 4 * 4);   // launches 1..3
    conv3x3_kernel<true><<<g128, 256>>>(cond, w1T, b1, f1, 261, 128);
    conv3x3_kernel<true><<<g128, 256>>>(f1, w2T, b2, f2, 128, 128);
    conv3x3_kernel<true><<<g128, 256>>>(f2, w3T, b3, f1, 128, 128);

    dim3 ghead(4, 16, 4 * 1);  // launch 4
    conv3x3_kernel<false><<<ghead, 256>>>(f1, w4T, b4p, headp, 128, 32);

    dim3 gdef(8, 32, 4);       // launch 5 -> captured by ncu -s 5 -c 1
    deform_kernel<<<gdef, 256, DEF_SMEM>>>(xtp, headp, flow, wdT, bd, out);
}

// round 13
// speedup vs baseline: 1.0089x; 1.0005x over previous
#include <cuda_runtime.h>
#include <cstdint>
#include <math.h>

#define HH 128
#define WW 128
#define HWSZ (HH*WW)
#define BB 4
#define CINC 128
#define COUTC 128

typedef unsigned long long ull;

// ---------- packed f32x2 helpers (sm_100+ PTX) ----------
__device__ __forceinline__ ull ffma2(ull a, ull b, ull c) {
    ull d;
    asm("fma.rn.f32x2 %0, %1, %2, %3;" : "=l"(d) : "l"(a), "l"(b), "l"(c));
    return d;
}
__device__ __forceinline__ ull pack2(float x, float y) {
    ull r;
    unsigned xi = __float_as_uint(x), yi = __float_as_uint(y);
    asm("mov.b64 %0, {%1, %2};" : "=l"(r) : "r"(xi), "r"(yi));
    return r;
}
__device__ __forceinline__ void unpack2(ull v, float& x, float& y) {
    unsigned xi, yi;
    asm("mov.b64 {%0, %1}, %2;" : "=r"(xi), "=r"(yi) : "l"(v));
    x = __uint_as_float(xi);
    y = __uint_as_float(yi);
}

// ---------- scratch (no allocations allowed -> __device__ globals) ----------
__device__ float g_f1[BB * COUTC * HWSZ];        // 32 MB
__device__ float g_f2[BB * COUTC * HWSZ];        // 32 MB
__device__ float g_xt[BB * CINC * HWSZ];         // 32 MB : x in NHWC [b][pix][c]
__device__ float g_head[BB * 32 * HWSZ];         // 8 MB (27 used, padded to 32)
__device__ float g_w1T[261 * 9 * 128];
__device__ float g_w2T[128 * 9 * 128];
__device__ float g_w3T[128 * 9 * 128];
__device__ float g_w4T[128 * 9 * 32];
__device__ float g_wdT[128 * 9 * 128];
__device__ float g_b4p[32];

// ---------- fused prep: NHWC transpose of x + all weight transposes + bias pad ----
// region A (blocks [0, 8192)): x NCHW -> NHWC via 32x32 smem tiles
// region B (rest): OIHW -> [cin][k][cout_pad] for w1..w4, wd; pad b4.
#define NHWC_BLOCKS 8192
#define N1T (261*9*128)
#define N2T (128*9*128)
#define N4T (128*9*32)
#define PREP_TOTAL (N1T + 3*N2T + N4T + 32)
#define PREP_BLOCKS ((PREP_TOTAL + 255) / 256)

__device__ __forceinline__ void wtrans_one(long i, const float* __restrict__ w,
                                           float* __restrict__ wT,
                                           int Cout, int Cin, int CoutPad) {
    int co = (int)(i % CoutPad);
    long t = i / CoutPad;
    int k = (int)(t % 9);
    int ci = (int)(t / 9);
    wT[i] = (co < Cout) ? w[((size_t)co * Cin + ci) * 9 + k] : 0.f;
}

__global__ void prep_kernel(const float* __restrict__ x, float* __restrict__ xt,
                            const float* __restrict__ w1, const float* __restrict__ w2,
                            const float* __restrict__ w3, const float* __restrict__ w4,
                            const float* __restrict__ wd, const float* __restrict__ b4,
                            float* __restrict__ w1T, float* __restrict__ w2T,
                            float* __restrict__ w3T, float* __restrict__ w4T,
                            float* __restrict__ wdT, float* __restrict__ b4p) {
    if (blockIdx.x < NHWC_BLOCKS) {
        __shared__ float t[32][33];
        int bid = blockIdx.x;
        int pT = bid & 511;
        int cT = (bid >> 9) & 3;
        int b  = bid >> 11;
        int tx = threadIdx.x & 31;
        int ty = threadIdx.x >> 5;           // 0..7
        int p0 = pT * 32, c0 = cT * 32;
        const float* ib = x + (size_t)b * CINC * HWSZ;
        float* ob = xt + (size_t)b * HWSZ * CINC;
        #pragma unroll
        for (int i = 0; i < 4; ++i)
            t[ty + 8 * i][tx] = ib[(size_t)(c0 + ty + 8 * i) * HWSZ + p0 + tx];
        __syncthreads();
        #pragma unroll
        for (int i = 0; i < 4; ++i)
            ob[(size_t)(p0 + ty + 8 * i) * CINC + c0 + tx] = t[tx][ty + 8 * i];
    } else {
        long i = (long)(blockIdx.x - NHWC_BLOCKS) * 256 + threadIdx.x;
        if (i >= PREP_TOTAL) return;
        if (i < N1T) { wtrans_one(i, w1, w1T, 128, 261, 128); return; }
        i -= N1T;
        if (i < N2T) { wtrans_one(i, w2, w2T, 128, 128, 128); return; }
        i -= N2T;
        if (i < N2T) { wtrans_one(i, w3, w3T, 128, 128, 128); return; }
        i -= N2T;
        if (i < N2T) { wtrans_one(i, wd, wdT, 128, 128, 128); return; }
        i -= N2T;
        if (i < N4T) { wtrans_one(i, w4, w4T, 27, 128, 32); return; }
        i -= N4T;
        b4p[i] = (i < 27) ? b4[i] : 0.f;
    }
}

// ---------- conv3x3 (SAME, stride 1), f32x2 register tile, ping-pong smem ----------
// block tile: 8 rows x 32 cols x 32 couts; thread: 4 px (W) x 8 couts.
template <bool LRELU>
__global__ __launch_bounds__(256, 2)
void conv3x3_kernel(const float* __restrict__ in, const float* __restrict__ wT,
                    const float* __restrict__ bias, float* __restrict__ out,
                    int Cin, int CoutTot) {
    __shared__ __align__(16) float xs[2][8][10][35];
    __shared__ __align__(16) float ws[2][8][9][32];

    const int tid = threadIdx.x;
    const int tx4 = (tid & 7) * 4;
    const int ty  = (tid >> 3) & 7;
    const int cz  = tid >> 6;
    const int x0 = blockIdx.x * 32;
    const int y0 = blockIdx.y * 8;
    const int ncg = CoutTot >> 5;
    const int b  = blockIdx.z / ncg;
    const int cg = blockIdx.z - b * ncg;
    const int cbase = cg * 32;

    ull acc[4][4];
    #pragma unroll
    for (int p = 0; p < 4; ++p)
        #pragma unroll
        for (int px = 0; px < 4; ++px) acc[p][px] = 0ull;

    const int nch = (Cin + 7) >> 3;

    auto stage = [&](int ch, int buf) {
        const int c0 = ch * 8;
        for (int i = tid; i < 8 * 10 * 34; i += 256) {
            int c = i / 340;
            int rm = i - c * 340;
            int r = rm / 34;
            int col = rm - r * 34;
            int ci = c0 + c;
            int gy = y0 - 1 + r;
            int gx = x0 - 1 + col;
            float v = 0.f;
            if (ci < Cin && (unsigned)gy < (unsigned)HH && (unsigned)gx < (unsigned)WW)
                v = in[((size_t)(b * Cin + ci) * HH + gy) * WW + gx];
            xs[buf][c][r][col] = v;
        }
        for (int i = tid; i < 8 * 9 * 32; i += 256) {
            int c = i / 288;
            int rm = i - c * 288;
            int k = rm >> 5;
            int co = rm & 31;
            int ci = c0 + c;
            ws[buf][c][k][co] = (ci < Cin) ? wT[(size_t)(ci * 9 + k) * CoutTot + cbase + co] : 0.f;
        }
    };

    stage(0, 0);
    __syncthreads();

    for (int ch = 0; ch < nch; ++ch) {
        const int cur = ch & 1;
        if (ch + 1 < nch) stage(ch + 1, cur ^ 1);   // overlaps other warps' compute

        #pragma unroll 1
        for (int c = 0; c < 8; ++c) {
            ull pin[3][6];
            #pragma unroll
            for (int r = 0; r < 3; ++r)
                #pragma unroll
                for (int j = 0; j < 6; ++j) {
                    float v = xs[cur][c][ty + r][tx4 + j];
                    pin[r][j] = pack2(v, v);
                }
            #pragma unroll
            for (int k = 0; k < 9; ++k) {
                const int r = k / 3, s = k - 3 * (k / 3);
                const ull* wp = (const ull*)&ws[cur][c][k][cz * 8];
                ull w0 = wp[0], w1 = wp[1], w2 = wp[2], w3 = wp[3];
                #pragma unroll
                for (int px = 0; px < 4; ++px) {
                    ull v = pin[r][s + px];
                    acc[0][px] = ffma2(v, w0, acc[0][px]);
                    acc[1][px] = ffma2(v, w1, acc[1][px]);
                    acc[2][px] = ffma2(v, w2, acc[2][px]);
                    acc[3][px] = ffma2(v, w3, acc[3][px]);
                }
            }
        }
        __syncthreads();
    }

    const int y = y0 + ty;
    #pragma unroll
    for (int p = 0; p < 4; ++p) {
        int co = cbase + cz * 8 + 2 * p;
        float blo = bias[co], bhi = bias[co + 1];
        float4 vlo, vhi;
        float a, bb2;
        unpack2(acc[p][0], a, bb2); vlo.x = a + blo; vhi.x = bb2 + bhi;
        unpack2(acc[p][1], a, bb2); vlo.y = a + blo; vhi.y = bb2 + bhi;
        unpack2(acc[p][2], a, bb2); vlo.z = a + blo; vhi.z = bb2 + bhi;
        unpack2(acc[p][3], a, bb2); vlo.w = a + blo; vhi.w = bb2 + bhi;
        if (LRELU) {
            vlo.x = vlo.x >= 0.f ? vlo.x : 0.1f * vlo.x;
            vlo.y = vlo.y >= 0.f ? vlo.y : 0.1f * vlo.y;
            vlo.z = vlo.z >= 0.f ? vlo.z : 0.1f * vlo.z;
            vlo.w = vlo.w >= 0.f ? vlo.w : 0.1f * vlo.w;
            vhi.x = vhi.x >= 0.f ? vhi.x : 0.1f * vhi.x;
            vhi.y = vhi.y >= 0.f ? vhi.y : 0.1f * vhi.y;
            vhi.z = vhi.z >= 0.f ? vhi.z : 0.1f * vhi.z;
            vhi.w = vhi.w >= 0.f ? vhi.w : 0.1f * vhi.w;
        }
        float* o0 = out + ((size_t)(b * CoutTot + co) * HH + y) * WW + x0 + tx4;
        *(float4*)o0 = vlo;
        *(float4*)(o0 + HWSZ) = vhi;
    }
}

// ---------- modulated deformable conv, NHWC gather + ping-pong ----------
// block tile: 16 (W) x 4 (H) pixels x all 128 couts; thread: 2 px x 16 couts.
// dynamic smem layout:
//   sw    float4[576]            9216 B
//   sidx  int4[576]              9216 B
//   wsm   float[2][4*9*128]     36864 B
//   ssm   float4[2][576]        18432 B   ([k*64+p] -> 4 channels)
#define DEF_SMEM (9216 + 9216 + 36864 + 18432)

__global__ __launch_bounds__(256, 2)
void deform_kernel(const float* __restrict__ xt, const float* __restrict__ head,
                   const float* __restrict__ flow, const float* __restrict__ wdT,
                   const float* __restrict__ bias, float* __restrict__ out) {
    extern __shared__ char dsm_raw[];
    float4* sw  = (float4*)dsm_raw;
    int4*  sidx = (int4*)(dsm_raw + 9216);
    float* wsm  = (float*)(dsm_raw + 18432);
    float4* ssm = (float4*)(dsm_raw + 18432 + 36864);

    const int tid = threadIdx.x;
    const int b = blockIdx.z;
    const int x0 = blockIdx.x * 16;
    const int y0 = blockIdx.y * 4;

    // phase 0: per-(tap, pixel) sampling parameters
    for (int e = tid; e < 576; e += 256) {
        int k = e >> 6;
        int p = e & 63;
        int y = y0 + (p >> 4);
        int xx = x0 + (p & 15);
        int pix = y * WW + xx;
        const float* hb = head + (size_t)b * 32 * HWSZ + pix;
        float dyr = hb[(2 * k) * HWSZ];
        float dxr = hb[(2 * k + 1) * HWSZ];
        float mr  = hb[(18 + k) * HWSZ];
        const float* fb = flow + (size_t)b * 2 * HWSZ + pix;
        float fx = fb[0];
        float fy = fb[HWSZ];
        float py = (float)(y - 1 + k / 3) + 3.0f * tanhf(dyr) + fy;
        float px = (float)(xx - 1 + (k - 3 * (k / 3))) + 3.0f * tanhf(dxr) + fx;
        float m = 1.0f / (1.0f + __expf(-mr));
        float fy0 = floorf(py), fx0 = floorf(px);
        float ay = py - fy0, ax = px - fx0;
        int iy0 = (int)fy0, ix0 = (int)fx0;
        int iy1 = iy0 + 1, ix1 = ix0 + 1;
        float vy0 = (iy0 >= 0 && iy0 < HH) ? m : 0.f;
        float vy1 = (iy1 >= 0 && iy1 < HH) ? m : 0.f;
        float vx0 = (ix0 >= 0 && ix0 < WW) ? 1.f : 0.f;
        float vx1 = (ix1 >= 0 && ix1 < WW) ? 1.f : 0.f;
        float w00 = (1.f - ay) * (1.f - ax) * vy0 * vx0;
        float w01 = (1.f - ay) * ax * vy0 * vx1;
        float w10 = ay * (1.f - ax) * vy1 * vx0;
        float w11 = ay * ax * vy1 * vx1;
        int cy0 = min(max(iy0, 0), HH - 1), cy1 = min(max(iy1, 0), HH - 1);
        int cx0 = min(max(ix0, 0), WW - 1), cx1 = min(max(ix1, 0), WW - 1);
        sw[e] = make_float4(w00, w01, w10, w11);
        sidx[e] = make_int4(cy0 * WW + cx0, cy0 * WW + cx1, cy1 * WW + cx0, cy1 * WW + cx1);
    }

    const int g = tid >> 5;    // 0..7 -> couts g*16..g*16+15
    const int ph = tid & 31;   // pixels ph and ph+32

    ull acc[2][8];
    #pragma unroll
    for (int q = 0; q < 8; ++q) {
        float b0 = bias[g * 16 + 2 * q];
        float b1 = bias[g * 16 + 2 * q + 1];
        acc[0][q] = pack2(b0, b1);
        acc[1][q] = pack2(b0, b1);
    }

    const float* xb = xt + (size_t)b * HWSZ * CINC;   // NHWC [pix][c]

    auto stage = [&](int c0, int buf) {
        // chunk weights: 4 cin x 9 k x 128 co, contiguous in wdT
        const float4* wsrc = (const float4*)(wdT + (size_t)c0 * 9 * 128);
        float4* wdst = (float4*)(wsm + buf * 4608);
        for (int i = tid; i < 1152; i += 256) wdst[i] = wsrc[i];
        // bilinear gather: per (k,p), one LDG.128 per corner covers 4 channels
        float4* sd = ssm + buf * 576;
        for (int e = tid; e < 576; e += 256) {
            float4 wv = sw[e];
            int4 iv = sidx[e];
            float4 v00 = __ldg((const float4*)(xb + (size_t)iv.x * CINC + c0));
            float4 v01 = __ldg((const float4*)(xb + (size_t)iv.y * CINC + c0));
            float4 v10 = __ldg((const float4*)(xb + (size_t)iv.z * CINC + c0));
            float4 v11 = __ldg((const float4*)(xb + (size_t)iv.w * CINC + c0));
            float4 r;
            r.x = wv.x * v00.x + wv.y * v01.x + wv.z * v10.x + wv.w * v11.x;
            r.y = wv.x * v00.y + wv.y * v01.y + wv.z * v10.y + wv.w * v11.y;
            r.z = wv.x * v00.z + wv.y * v01.z + wv.z * v10.z + wv.w * v11.z;
            r.w = wv.x * v00.w + wv.y * v01.w + wv.z * v10.w + wv.w * v11.w;
            sd[e] = r;
        }
    };

    __syncthreads();          // sw/sidx visible
    stage(0, 0);
    __syncthreads();

    for (int ci = 0; ci < 32; ++ci) {
        const int cur = ci & 1;
        if (ci + 1 < 32) stage((ci + 1) * 4, cur ^ 1);

        const float* wsmb = wsm + cur * 4608;
        const float4* ssmb = ssm + cur * 576;
        #pragma unroll
        for (int k = 0; k < 9; ++k) {
            float4 s0 = ssmb[k * 64 + ph];          // px0 = ph (stride 16B: conflict-free)
            float4 s1 = ssmb[k * 64 + ph + 32];     // px1 = ph+32
            #pragma unroll
            for (int c = 0; c < 4; ++c) {
                float f0 = (&s0.x)[c];
                float f1 = (&s1.x)[c];
                ull a0 = pack2(f0, f0);
                ull a1 = pack2(f1, f1);
                const float4* wrow = (const float4*)(wsmb + (c * 9 + k) * 128 + g * 16);
                #pragma unroll
                for (int q4 = 0; q4 < 4; ++q4) {
                    float4 wv = wrow[q4];
                    ull w01 = pack2(wv.x, wv.y);
                    ull w23 = pack2(wv.z, wv.w);
                    acc[0][2 * q4]     = ffma2(a0, w01, acc[0][2 * q4]);
                    acc[0][2 * q4 + 1] = ffma2(a0, w23, acc[0][2 * q4 + 1]);
                    acc[1][2 * q4]     = ffma2(a1, w01, acc[1][2 * q4]);
                    acc[1][2 * q4 + 1] = ffma2(a1, w23, acc[1][2 * q4 + 1]);
                }
            }
        }
        __syncthreads();
    }

    // epilogue: 16 couts x 2 px (ph, ph+32 -> rows y, y+2)
    int yy0 = y0 + (ph >> 4);
    int xx0 = x0 + (ph & 15);
    #pragma unroll
    for (int q = 0; q < 8; ++q) {
        int co = g * 16 + 2 * q;
        float a0, a1, c0v, c1v;
        unpack2(acc[0][q], a0, a1);
        unpack2(acc[1][q], c0v, c1v);
        float* o = out + ((size_t)(b * COUTC + co) * HH + yy0) * WW + xx0;
        o[0] = a0;
        o[HWSZ] = a1;
        o[2 * WW] = c0v;
        o[HWSZ + 2 * WW] = c1v;
    }
}

// ---------- launcher ----------
extern "C" void kernel_launch(void* const* d_in, const int* in_sizes, int n_in,
                              void* d_out, int out_size) {
    const float* x    = (const float*)d_in[0];
    const float* cond = (const float*)d_in[1];
    const float* flow = (const float*)d_in[2];
    const float* w1 = (const float*)d_in[3];
    const float* b1 = (const float*)d_in[4];
    const float* w2 = (const float*)d_in[5];
    const float* b2 = (const float*)d_in[6];
    const float* w3 = (const float*)d_in[7];
    const float* b3 = (const float*)d_in[8];
    const float* w4 = (const float*)d_in[9];
    const float* b4 = (const float*)d_in[10];
    const float* wd = (const float*)d_in[11];
    const float* bd = (const float*)d_in[12];
    float* out = (float*)d_out;

    float *f1, *f2, *xtp, *headp, *w1T, *w2T, *w3T, *w4T, *wdT, *b4p;
    cudaGetSymbolAddress((void**)&f1,    g_f1);
    cudaGetSymbolAddress((void**)&f2,    g_f2);
    cudaGetSymbolAddress((void**)&xtp,   g_xt);
    cudaGetSymbolAddress((void**)&headp, g_head);
    cudaGetSymbolAddress((void**)&w1T,   g_w1T);
    cudaGetSymbolAddress((void**)&w2T,   g_w2T);
    cudaGetSymbolAddress((void**)&w3T,   g_w3T);
    cudaGetSymbolAddress((void**)&w4T,   g_w4T);
    cudaGetSymbolAddress((void**)&wdT,   g_wdT);
    cudaGetSymbolAddress((void**)&b4p,   g_b4p);

    cudaFuncSetAttribute(deform_kernel, cudaFuncAttributeMaxDynamicSharedMemorySize, DEF_SMEM);

    // launch 0: fused prep (NHWC transpose + all weight prep)
    prep_kernel<<<NHWC_BLOCKS + PREP_BLOCKS, 256>>>(
        x, xtp, w1, w2, w3, w4, wd, b4, w1T, w2T, w3T, w4T, wdT, b4p);

    dim3 g128(4, 16, 4 * 4);   // launches 1..3
    conv3x3_kernel<true><<<g128, 256>>>(cond, w1T, b1, f1, 261, 128);
    conv3x3_kernel<true><<<g128, 256>>>(f1, w2T, b2, f2, 128, 128);
    conv3x3_kernel<true><<<g128, 256>>>(f2, w3T, b3, f1, 128, 128);

    dim3 ghead(4, 16, 4 * 1);  // launch 4
    conv3x3_kernel<false><<<ghead, 256>>>(f1, w4T, b4p, headp, 128, 32);

    dim3 gdef(8, 32, 4);       // launch 5 -> captured by ncu -s 5 -c 1
    deform_kernel<<<gdef, 256, DEF_SMEM>>>(xtp, headp, flow, wdT, bd, out);
}

// round 15
// speedup vs baseline: 1.7348x; 1.7194x over previous
#include <cuda_runtime.h>
#include <cuda_bf16.h>
#include <cstdint>
#include <math.h>

#define HH 128
#define WW 128
#define HWSZ (HH*WW)
#define BB 4

typedef unsigned long long ull;
typedef __nv_bfloat16 bf16;

// ---------------- scalar f32x2 helpers ----------------
__device__ __forceinline__ ull ffma2(ull a, ull b, ull c) {
    ull d; asm("fma.rn.f32x2 %0, %1, %2, %3;" : "=l"(d) : "l"(a), "l"(b), "l"(c)); return d;
}
__device__ __forceinline__ ull pack2(float x, float y) {
    ull r; unsigned xi = __float_as_uint(x), yi = __float_as_uint(y);
    asm("mov.b64 %0, {%1, %2};" : "=l"(r) : "r"(xi), "r"(yi)); return r;
}
__device__ __forceinline__ void unpack2(ull v, float& x, float& y) {
    unsigned xi, yi; asm("mov.b64 {%0, %1}, %2;" : "=r"(xi), "=r"(yi) : "l"(v));
    x = __uint_as_float(xi); y = __uint_as_float(yi);
}

// ---------------- HMMA helpers (baseline PTX, sm_80+) ----------------
__device__ __forceinline__ uint32_t s2u(const void* p) {
    uint32_t a;
    asm("{ .reg .u64 t; cvta.to.shared.u64 t, %1; cvt.u32.u64 %0, t; }" : "=r"(a) : "l"(p));
    return a;
}
__device__ __forceinline__ void ldsm4(uint32_t* r, uint32_t addr) {
    asm volatile("ldmatrix.sync.aligned.m8n8.x4.shared.b16 {%0,%1,%2,%3}, [%4];"
        : "=r"(r[0]), "=r"(r[1]), "=r"(r[2]), "=r"(r[3]) : "r"(addr));
}
__device__ __forceinline__ void mma16816(float* d, const uint32_t* a, uint32_t b0, uint32_t b1) {
    asm volatile("mma.sync.aligned.m16n8k16.row.col.f32.bf16.bf16.f32 "
        "{%0,%1,%2,%3}, {%4,%5,%6,%7}, {%8,%9}, {%0,%1,%2,%3};"
        : "+f"(d[0]), "+f"(d[1]), "+f"(d[2]), "+f"(d[3])
        : "r"(a[0]), "r"(a[1]), "r"(a[2]), "r"(a[3]), "r"(b0), "r"(b1));
}

// ---------------- scratch globals ----------------
#define C1P 288                       // conv1 input channels padded (261 -> 288)
__device__ __align__(16) float g_xt[BB * 128 * HWSZ];       // x NHWC fp32 (deform gather)
__device__ __align__(16) bf16  g_ch[BB * HWSZ * C1P];       // cond NHWC hi
__device__ __align__(16) bf16  g_cl[BB * HWSZ * C1P];       // cond NHWC lo
__device__ __align__(16) bf16  g_ah[BB * HWSZ * 128], g_al[BB * HWSZ * 128];
__device__ __align__(16) bf16  g_bh[BB * HWSZ * 128], g_bl[BB * HWSZ * 128];
__device__ __align__(16) float g_head[BB * HWSZ * 32];      // head NHWC fp32 (27 used)
// weight tiles: [ch][tap][sp][co][24ci] bf16 (16 used + 8 pad per row)
__device__ __align__(16) bf16  g_wt1[18*9*2*128*24];
__device__ __align__(16) bf16  g_wt2[8*9*2*128*24];
__device__ __align__(16) bf16  g_wt3[8*9*2*128*24];
__device__ __align__(16) bf16  g_wt4[8*9*2*32*24];
__device__ __align__(16) float g_wdT[128 * 9 * 128];        // [ci][k][co]
__device__ float g_b4p[32];

// ---------------- prep ----------------
#define R1B 8192
#define R2B (4*512*9)
#define W1E (18*9*2*128*24)
#define W2E (8*9*2*128*24)
#define W4E (8*9*2*32*24)
#define WDE (128*9*128)
#define W1BLK (W1E/256)
#define W2BLK (W2E/256)
#define W4BLK (W4E/256)
#define WDBLK (WDE/256)
#define PREP_NB (R1B + R2B + W1BLK + 2*W2BLK + W4BLK + WDBLK + 1)

__device__ __forceinline__ void wtile_one(int i, const float* __restrict__ w,
                                          bf16* __restrict__ dst, int Cin, int Cout, int NCO) {
    int ci = i % 24; int t = i / 24;
    int co = t % NCO; t /= NCO;
    int sp = t & 1; t >>= 1;
    int tap = t % 9; int ch = t / 9;
    int cig = ch * 16 + ci;
    float v = (ci < 16 && cig < Cin && co < Cout) ? w[((size_t)co * Cin + cig) * 9 + tap] : 0.f;
    bf16 h = __float2bfloat16(v);
    dst[i] = sp ? __float2bfloat16(v - __bfloat162float(h)) : h;
}

__global__ void prep_kernel(const float* __restrict__ x, const float* __restrict__ cond,
                            const float* __restrict__ w1, const float* __restrict__ w2,
                            const float* __restrict__ w3, const float* __restrict__ w4,
                            const float* __restrict__ wd, const float* __restrict__ b4) {
    int blk = blockIdx.x, tid = threadIdx.x;
    if (blk < R1B) {                                // x NCHW -> NHWC fp32
        __shared__ float t[32][33];
        int pT = blk & 511, cT = (blk >> 9) & 3, b = blk >> 11;
        int tx = tid & 31, ty = tid >> 5;
        int p0 = pT * 32, c0 = cT * 32;
        const float* ib = x + (size_t)b * 128 * HWSZ;
        float* ob = g_xt + (size_t)b * HWSZ * 128;
        #pragma unroll
        for (int i = 0; i < 4; ++i)
            t[ty + 8 * i][tx] = ib[(size_t)(c0 + ty + 8 * i) * HWSZ + p0 + tx];
        __syncthreads();
        #pragma unroll
        for (int i = 0; i < 4; ++i)
            ob[(size_t)(p0 + ty + 8 * i) * 128 + c0 + tx] = t[tx][ty + 8 * i];
        return;
    }
    blk -= R1B;
    if (blk < R2B) {                                // cond -> NHWC bf16 hi/lo pad C1P
        __shared__ float t[32][33];
        int ct = blk % 9, pt = (blk / 9) & 511, b = blk / 4608;
        int tx = tid & 31, ty = tid >> 5;
        int c0 = ct * 32, p0 = pt * 32;
        #pragma unroll
        for (int i = 0; i < 4; ++i) {
            int c = c0 + ty + 8 * i;
            t[ty + 8 * i][tx] = (c < 261) ? cond[((size_t)(b * 261 + c) << 14) + p0 + tx] : 0.f;
        }
        __syncthreads();
        #pragma unroll
        for (int i = 0; i < 4; ++i) {
            float v = t[tx][ty + 8 * i];
            bf16 h = __float2bfloat16(v);
            size_t o = ((size_t)(b << 14) + p0 + ty + 8 * i) * C1P + c0 + tx;
            g_ch[o] = h;
            g_cl[o] = __float2bfloat16(v - __bfloat162float(h));
        }
        return;
    }
    blk -= R2B;
    if (blk < W1BLK) { wtile_one(blk * 256 + tid, w1, g_wt1, 261, 128, 128); return; }
    blk -= W1BLK;
    if (blk < W2BLK) { wtile_one(blk * 256 + tid, w2, g_wt2, 128, 128, 128); return; }
    blk -= W2BLK;
    if (blk < W2BLK) { wtile_one(blk * 256 + tid, w3, g_wt3, 128, 128, 128); return; }
    blk -= W2BLK;
    if (blk < W4BLK) { wtile_one(blk * 256 + tid, w4, g_wt4, 128, 27, 32); return; }
    blk -= W4BLK;
    if (blk < WDBLK) {
        int i = blk * 256 + tid;
        int co = i & 127, t = i >> 7;
        g_wdT[i] = wd[((size_t)co * 128 + (t / 9)) * 9 + (t % 9)];
        return;
    }
    if (tid < 32) g_b4p[tid] = (tid < 27) ? b4[tid] : 0.f;
}

// ---------------- conv3x3 via mma.sync bf16 (hi/lo split, 3 combos) ----------------
// Block: M=128 px (one row y0) x N=NCO. A strip [3 rows][132 px][16 ci] serves all 9 taps.
// B tiles [co][24 ci] double-buffered. 48B row stride -> conflict-free LDSM.
// MODE 0: bias+lrelu -> bf16 hi/lo NHWC (stride 128). MODE 1: bias -> fp32 NHWC (stride 32).
template <int NCO, int NCH, int CINP, int MODE>
__global__ __launch_bounds__(256, 2)
void conv_mma(const bf16* __restrict__ ih, const bf16* __restrict__ il,
              const bf16* __restrict__ wt, const float* __restrict__ bias,
              bf16* __restrict__ oh, bf16* __restrict__ ol, float* __restrict__ of) {
    constexpr int NWN = (NCO == 128) ? 2 : 1;   // warps along N
    constexpr int NM  = (NCO == 128) ? 2 : 1;   // m16 tiles per warp
    constexpr int NN  = (NCO == 128) ? 8 : 4;   // n8 tiles per warp
    constexpr int ASP = 3 * 132 * 48;           // bytes per A split (19008)
    constexpr int BSP = NCO * 48;               // bytes per B split
    constexpr int BBUF = 2 * BSP;

    extern __shared__ char sm[];
    __shared__ float s_bias[NCO];
    char* As = sm;
    char* Bs = sm + 2 * ASP;

    const int tid = threadIdx.x, wid = tid >> 5, lane = tid & 31;
    const int y0 = blockIdx.x, b = blockIdx.y;
    const size_t bofs = (size_t)b * HWSZ;
    if (tid < NCO) s_bias[tid] = bias[tid];

    const int wm = (wid / NWN) * (NM * 16);
    const int wn = (wid % NWN) * (NN * 8);
    const uint32_t Asb = s2u(sm);
    const uint32_t Bsb = Asb + 2 * ASP;

    float d[NM][NN][4];
    #pragma unroll
    for (int m = 0; m < NM; ++m)
        #pragma unroll
        for (int j = 0; j < NN; ++j)
            #pragma unroll
            for (int q = 0; q < 4; ++q) d[m][j][q] = 0.f;

    auto stageB = [&](int ch, int tap, int buf) {
        const uint4* src = (const uint4*)(wt + (size_t)((ch * 9 + tap) * 2) * NCO * 24);
        uint4* dst = (uint4*)(Bs + buf * BBUF);
        #pragma unroll
        for (int i = tid; i < NCO * 6; i += 256) dst[i] = src[i];
    };

    for (int ch = 0; ch < NCH; ++ch) {
        // stage A strip: [sp][r(3)][px(132)][16 ci], zeros at borders
        for (int e = tid; e < 1584; e += 256) {
            int sp = e / 792, f = e - sp * 792;
            int half = f & 1, rp = f >> 1;
            int r = rp / 132, px = rp - r * 132;
            int iy = y0 + r - 1, ix = px - 1;
            uint4 v = make_uint4(0, 0, 0, 0);
            if ((unsigned)iy < 128u && (unsigned)ix < 128u)
                v = *(const uint4*)((sp ? il : ih) +
                    (bofs + (size_t)iy * WW + ix) * CINP + ch * 16 + half * 8);
            *(uint4*)(As + sp * ASP + rp * 48 + half * 16) = v;
        }
        stageB(ch, 0, 0);
        __syncthreads();

        for (int tap = 0; tap < 9; ++tap) {
            if (tap < 8) stageB(ch, tap + 1, (tap + 1) & 1);

            const int dy = tap / 3 - 1, dx = tap % 3 - 1;
            uint32_t ah[NM][4], al[NM][4];
            const int arow = (dy + 1) * 132;
            #pragma unroll
            for (int m = 0; m < NM; ++m) {
                uint32_t aa = Asb + (uint32_t)(arow + wm + m * 16 + dx + 1 + (lane & 15)) * 48
                            + (lane >> 4) * 16;
                ldsm4(ah[m], aa);
                ldsm4(al[m], aa + ASP);
            }
            const uint32_t bq = Bsb + (tap & 1) * BBUF;
            const uint32_t boff = (uint32_t)((lane & 7) + ((lane >> 4) << 3)) * 48
                                + ((lane >> 3) & 1) * 16;
            uint32_t bb[NN / 2][4];
            #pragma unroll
            for (int nt = 0; nt < NN / 2; ++nt)
                ldsm4(bb[nt], bq + (uint32_t)(wn + nt * 16) * 48 + boff);
            #pragma unroll
            for (int m = 0; m < NM; ++m)
                #pragma unroll
                for (int j = 0; j < NN; ++j) {
                    uint32_t b0 = bb[j >> 1][(j & 1) * 2], b1 = bb[j >> 1][(j & 1) * 2 + 1];
                    mma16816(d[m][j], ah[m], b0, b1);   // ah * bh
                    mma16816(d[m][j], al[m], b0, b1);   // al * bh
                }
            #pragma unroll
            for (int nt = 0; nt < NN / 2; ++nt)
                ldsm4(bb[nt], bq + BSP + (uint32_t)(wn + nt * 16) * 48 + boff);
            #pragma unroll
            for (int m = 0; m < NM; ++m)
                #pragma unroll
                for (int j = 0; j < NN; ++j)
                    mma16816(d[m][j], ah[m], bb[j >> 1][(j & 1) * 2], bb[j >> 1][(j & 1) * 2 + 1]); // ah * bl
            __syncthreads();
        }
    }

    // epilogue
    const int g = lane >> 2, tig = lane & 3;
    #pragma unroll
    for (int m = 0; m < NM; ++m) {
        #pragma unroll
        for (int j = 0; j < NN; ++j) {
            int col = wn + j * 8 + 2 * tig;
            float blo = s_bias[col], bhi = s_bias[col + 1];
            #pragma unroll
            for (int hrow = 0; hrow < 2; ++hrow) {
                int xr = wm + m * 16 + g + hrow * 8;
                float v0 = d[m][j][hrow * 2] + blo;
                float v1 = d[m][j][hrow * 2 + 1] + bhi;
                size_t pix = bofs + (size_t)y0 * WW + xr;
                if (MODE == 0) {
                    v0 = v0 >= 0.f ? v0 : 0.1f * v0;
                    v1 = v1 >= 0.f ? v1 : 0.1f * v1;
                    bf16 h0 = __float2bfloat16(v0), h1 = __float2bfloat16(v1);
                    __nv_bfloat162 hv; hv.x = h0; hv.y = h1;
                    __nv_bfloat162 lv;
                    lv.x = __float2bfloat16(v0 - __bfloat162float(h0));
                    lv.y = __float2bfloat16(v1 - __bfloat162float(h1));
                    *(__nv_bfloat162*)(oh + pix * 128 + col) = hv;
                    *(__nv_bfloat162*)(ol + pix * 128 + col) = lv;
                } else {
                    *(float2*)(of + pix * 32 + col) = make_float2(v0, v1);
                }
            }
        }
    }
}

// ---------------- modulated deformable conv (f32x2, NHWC gather) ----------------
#define DEF_SMEM (9216 + 9216 + 36864 + 18432)

__global__ __launch_bounds__(256, 2)
void deform_kernel(const float* __restrict__ xt, const float* __restrict__ head,
                   const float* __restrict__ flow, const float* __restrict__ wdT,
                   const float* __restrict__ bias, float* __restrict__ out) {
    extern __shared__ char dsm_raw[];
    float4* sw = (float4*)dsm_raw;
    int4* sidx = (int4*)(dsm_raw + 9216);
    float* wsm = (float*)(dsm_raw + 18432);
    float4* ssm = (float4*)(dsm_raw + 18432 + 36864);

    const int tid = threadIdx.x;
    const int b = blockIdx.z;
    const int x0 = blockIdx.x * 16;
    const int y0 = blockIdx.y * 4;

    for (int e = tid; e < 576; e += 256) {
        int k = e >> 6, p = e & 63;
        int y = y0 + (p >> 4), xx = x0 + (p & 15);
        int pix = y * WW + xx;
        const float* hb = head + ((size_t)b * HWSZ + pix) * 32;     // NHWC head
        float dyr = hb[2 * k], dxr = hb[2 * k + 1], mr = hb[18 + k];
        const float* fb = flow + (size_t)b * 2 * HWSZ + pix;
        float fx = fb[0], fy = fb[HWSZ];
        float py = (float)(y - 1 + k / 3) + 3.0f * tanhf(dyr) + fy;
        float px = (float)(xx - 1 + (k - 3 * (k / 3))) + 3.0f * tanhf(dxr) + fx;
        float m = 1.0f / (1.0f + __expf(-mr));
        float fy0 = floorf(py), fx0 = floorf(px);
        float ay = py - fy0, ax = px - fx0;
        int iy0 = (int)fy0, ix0 = (int)fx0;
        int iy1 = iy0 + 1, ix1 = ix0 + 1;
        float vy0 = (iy0 >= 0 && iy0 < HH) ? m : 0.f;
        float vy1 = (iy1 >= 0 && iy1 < HH) ? m : 0.f;
        float vx0 = (ix0 >= 0 && ix0 < WW) ? 1.f : 0.f;
        float vx1 = (ix1 >= 0 && ix1 < WW) ? 1.f : 0.f;
        sw[e] = make_float4((1.f - ay) * (1.f - ax) * vy0 * vx0,
                            (1.f - ay) * ax * vy0 * vx1,
                            ay * (1.f - ax) * vy1 * vx0,
                            ay * ax * vy1 * vx1);
        int cy0 = min(max(iy0, 0), HH - 1), cy1 = min(max(iy1, 0), HH - 1);
        int cx0 = min(max(ix0, 0), WW - 1), cx1 = min(max(ix1, 0), WW - 1);
        sidx[e] = make_int4(cy0 * WW + cx0, cy0 * WW + cx1, cy1 * WW + cx0, cy1 * WW + cx1);
    }

    const int g = tid >> 5;
    const int ph = tid & 31;

    ull acc[2][8];
    #pragma unroll
    for (int q = 0; q < 8; ++q) {
        float b0 = bias[g * 16 + 2 * q], b1 = bias[g * 16 + 2 * q + 1];
        acc[0][q] = pack2(b0, b1);
        acc[1][q] = pack2(b0, b1);
    }

    const float* xb = xt + (size_t)b * HWSZ * 128;

    auto stage = [&](int c0, int buf) {
        const float4* wsrc = (const float4*)(wdT + (size_t)c0 * 9 * 128);
        float4* wdst = (float4*)(wsm + buf * 4608);
        for (int i = tid; i < 1152; i += 256) wdst[i] = wsrc[i];
        float4* sd = ssm + buf * 576;
        for (int e = tid; e < 576; e += 256) {
            float4 wv = sw[e];
            int4 iv = sidx[e];
            float4 v00 = __ldg((const float4*)(xb + (size_t)iv.x * 128 + c0));
            float4 v01 = __ldg((const float4*)(xb + (size_t)iv.y * 128 + c0));
            float4 v10 = __ldg((const float4*)(xb + (size_t)iv.z * 128 + c0));
            float4 v11 = __ldg((const float4*)(xb + (size_t)iv.w * 128 + c0));
            float4 r;
            r.x = wv.x * v00.x + wv.y * v01.x + wv.z * v10.x + wv.w * v11.x;
            r.y = wv.x * v00.y + wv.y * v01.y + wv.z * v10.y + wv.w * v11.y;
            r.z = wv.x * v00.z + wv.y * v01.z + wv.z * v10.z + wv.w * v11.z;
            r.w = wv.x * v00.w + wv.y * v01.w + wv.z * v10.w + wv.w * v11.w;
            sd[e] = r;
        }
    };

    __syncthreads();
    stage(0, 0);
    __syncthreads();

    for (int ci = 0; ci < 32; ++ci) {
        const int cur = ci & 1;
        if (ci + 1 < 32) stage((ci + 1) * 4, cur ^ 1);
        const float* wsmb = wsm + cur * 4608;
        const float4* ssmb = ssm + cur * 576;
        #pragma unroll
        for (int k = 0; k < 9; ++k) {
            float4 s0 = ssmb[k * 64 + ph];
            float4 s1 = ssmb[k * 64 + ph + 32];
            #pragma unroll
            for (int c = 0; c < 4; ++c) {
                float f0 = (&s0.x)[c], f1 = (&s1.x)[c];
                ull a0 = pack2(f0, f0), a1 = pack2(f1, f1);
                const float4* wrow = (const float4*)(wsmb + (c * 9 + k) * 128 + g * 16);
                #pragma unroll
                for (int q4 = 0; q4 < 4; ++q4) {
                    float4 wv = wrow[q4];
                    ull w01 = pack2(wv.x, wv.y), w23 = pack2(wv.z, wv.w);
                    acc[0][2 * q4]     = ffma2(a0, w01, acc[0][2 * q4]);
                    acc[0][2 * q4 + 1] = ffma2(a0, w23, acc[0][2 * q4 + 1]);
                    acc[1][2 * q4]     = ffma2(a1, w01, acc[1][2 * q4]);
                    acc[1][2 * q4 + 1] = ffma2(a1, w23, acc[1][2 * q4 + 1]);
                }
            }
        }
        __syncthreads();
    }

    int yy0 = y0 + (ph >> 4), xx0 = x0 + (ph & 15);
    #pragma unroll
    for (int q = 0; q < 8; ++q) {
        int co = g * 16 + 2 * q;
        float a0, a1, c0v, c1v;
        unpack2(acc[0][q], a0, a1);
        unpack2(acc[1][q], c0v, c1v);
        float* o = out + ((size_t)(b * 128 + co) * HH + yy0) * WW + xx0;
        o[0] = a0;
        o[HWSZ] = a1;
        o[2 * WW] = c0v;
        o[HWSZ + 2 * WW] = c1v;
    }
}

// ---------------- launcher ----------------
extern "C" void kernel_launch(void* const* d_in, const int* in_sizes, int n_in,
                              void* d_out, int out_size) {
    const float* x    = (const float*)d_in[0];
    const float* cond = (const float*)d_in[1];
    const float* flow = (const float*)d_in[2];
    const float* w1 = (const float*)d_in[3];
    const float* b1 = (const float*)d_in[4];
    const float* w2 = (const float*)d_in[5];
    const float* b2 = (const float*)d_in[6];
    const float* w3 = (const float*)d_in[7];
    const float* b3 = (const float*)d_in[8];
    const float* w4 = (const float*)d_in[9];
    const float* b4 = (const float*)d_in[10];
    const float* wd = (const float*)d_in[11];
    const float* bd = (const float*)d_in[12];
    float* out = (float*)d_out;

    float *xtp, *headp, *wdT, *b4p;
    bf16 *chp, *clp, *ahp, *alp, *bhp, *blp, *wt1, *wt2, *wt3, *wt4;
    cudaGetSymbolAddress((void**)&xtp, g_xt);
    cudaGetSymbolAddress((void**)&chp, g_ch);
    cudaGetSymbolAddress((void**)&clp, g_cl);
    cudaGetSymbolAddress((void**)&ahp, g_ah);
    cudaGetSymbolAddress((void**)&alp, g_al);
    cudaGetSymbolAddress((void**)&bhp, g_bh);
    cudaGetSymbolAddress((void**)&blp, g_bl);
    cudaGetSymbolAddress((void**)&headp, g_head);
    cudaGetSymbolAddress((void**)&wt1, g_wt1);
    cudaGetSymbolAddress((void**)&wt2, g_wt2);
    cudaGetSymbolAddress((void**)&wt3, g_wt3);
    cudaGetSymbolAddress((void**)&wt4, g_wt4);
    cudaGetSymbolAddress((void**)&wdT, g_wdT);
    cudaGetSymbolAddress((void**)&b4p, g_b4p);

    const int SM128 = 2 * (3 * 132 * 48) + 2 * 2 * 128 * 48;   // 38016 + 24576 = 62592
    const int SM32  = 2 * (3 * 132 * 48) + 2 * 2 * 32 * 48;    // 38016 + 6144  = 44160
    cudaFuncSetAttribute(conv_mma<128, 18, C1P, 0>, cudaFuncAttributeMaxDynamicSharedMemorySize, SM128);
    cudaFuncSetAttribute(conv_mma<128, 8, 128, 0>,  cudaFuncAttributeMaxDynamicSharedMemorySize, SM128);
    cudaFuncSetAttribute(conv_mma<32, 8, 128, 1>,   cudaFuncAttributeMaxDynamicSharedMemorySize, SM32);
    cudaFuncSetAttribute(deform_kernel, cudaFuncAttributeMaxDynamicSharedMemorySize, DEF_SMEM);

    prep_kernel<<<PREP_NB, 256>>>(x, cond, w1, w2, w3, w4, wd, b4);

    dim3 gc(128, BB);
    conv_mma<128, 18, C1P, 0><<<gc, 256, SM128>>>(chp, clp, wt1, b1, ahp, alp, nullptr);
    conv_mma<128, 8, 128, 0><<<gc, 256, SM128>>>(ahp, alp, wt2, b2, bhp, blp, nullptr);
    conv_mma<128, 8, 128, 0><<<gc, 256, SM128>>>(bhp, blp, wt3, b3, ahp, alp, nullptr);
    conv_mma<32, 8, 128, 1><<<gc, 256, SM32>>>(ahp, alp, wt4, b4p, nullptr, nullptr, headp);

    dim3 gdef(8, 32, 4);
    deform_kernel<<<gdef, 256, DEF_SMEM>>>(xtp, headp, flow, wdT, bd, out);
}

// round 16
// speedup vs baseline: 2.0347x; 1.1729x over previous
#include <cuda_runtime.h>
#include <cuda_bf16.h>
#include <cstdint>
#include <math.h>

#define HH 128
#define WW 128
#define HWSZ (HH*WW)
#define BB 4

typedef unsigned long long ull;
typedef __nv_bfloat16 bf16;

// ---------------- HMMA helpers (baseline PTX, sm_80+) ----------------
__device__ __forceinline__ uint32_t s2u(const void* p) {
    uint32_t a;
    asm("{ .reg .u64 t; cvta.to.shared.u64 t, %1; cvt.u32.u64 %0, t; }" : "=r"(a) : "l"(p));
    return a;
}
__device__ __forceinline__ void ldsm4(uint32_t* r, uint32_t addr) {
    asm volatile("ldmatrix.sync.aligned.m8n8.x4.shared.b16 {%0,%1,%2,%3}, [%4];"
        : "=r"(r[0]), "=r"(r[1]), "=r"(r[2]), "=r"(r[3]) : "r"(addr));
}
__device__ __forceinline__ void mma16816(float* d, const uint32_t* a, uint32_t b0, uint32_t b1) {
    asm volatile("mma.sync.aligned.m16n8k16.row.col.f32.bf16.bf16.f32 "
        "{%0,%1,%2,%3}, {%4,%5,%6,%7}, {%8,%9}, {%0,%1,%2,%3};"
        : "+f"(d[0]), "+f"(d[1]), "+f"(d[2]), "+f"(d[3])
        : "r"(a[0]), "r"(a[1]), "r"(a[2]), "r"(a[3]), "r"(b0), "r"(b1));
}

// ---------------- scratch globals ----------------
#define C1P 288                       // conv1 input channels padded (261 -> 288)
__device__ __align__(16) float g_xt[BB * 128 * HWSZ];       // x NHWC fp32 (deform gather)
__device__ __align__(16) bf16  g_ch[BB * HWSZ * C1P];       // cond NHWC hi
__device__ __align__(16) bf16  g_cl[BB * HWSZ * C1P];       // cond NHWC lo
__device__ __align__(16) bf16  g_ah[BB * HWSZ * 128], g_al[BB * HWSZ * 128];
__device__ __align__(16) bf16  g_bh[BB * HWSZ * 128], g_bl[BB * HWSZ * 128];
__device__ __align__(16) float g_head[BB * HWSZ * 32];      // head NHWC fp32 (27 used)
// weight tiles: [ch][tap][sp][co][24ci] bf16 (16 used + 8 pad per row)
__device__ __align__(16) bf16  g_wt1[18*9*2*128*24];
__device__ __align__(16) bf16  g_wt2[8*9*2*128*24];
__device__ __align__(16) bf16  g_wt3[8*9*2*128*24];
__device__ __align__(16) bf16  g_wt4[8*9*2*32*24];
__device__ __align__(16) bf16  g_wtd[8*9*2*128*24];         // deform weights, same tile format
__device__ float g_b4p[32];

// ---------------- prep ----------------
#define R1B 8192
#define R2B (4*512*9)
#define W1E (18*9*2*128*24)
#define W2E (8*9*2*128*24)
#define W4E (8*9*2*32*24)
#define W1BLK (W1E/256)
#define W2BLK (W2E/256)
#define W4BLK (W4E/256)
#define PREP_NB (R1B + R2B + W1BLK + 3*W2BLK + W4BLK + 1)

__device__ __forceinline__ void wtile_one(int i, const float* __restrict__ w,
                                          bf16* __restrict__ dst, int Cin, int Cout, int NCO) {
    int ci = i % 24; int t = i / 24;
    int co = t % NCO; t /= NCO;
    int sp = t & 1; t >>= 1;
    int tap = t % 9; int ch = t / 9;
    int cig = ch * 16 + ci;
    float v = (ci < 16 && cig < Cin && co < Cout) ? w[((size_t)co * Cin + cig) * 9 + tap] : 0.f;
    bf16 h = __float2bfloat16(v);
    dst[i] = sp ? __float2bfloat16(v - __bfloat162float(h)) : h;
}

__global__ void prep_kernel(const float* __restrict__ x, const float* __restrict__ cond,
                            const float* __restrict__ w1, const float* __restrict__ w2,
                            const float* __restrict__ w3, const float* __restrict__ w4,
                            const float* __restrict__ wd, const float* __restrict__ b4) {
    int blk = blockIdx.x, tid = threadIdx.x;
    if (blk < R1B) {                                // x NCHW -> NHWC fp32
        __shared__ float t[32][33];
        int pT = blk & 511, cT = (blk >> 9) & 3, b = blk >> 11;
        int tx = tid & 31, ty = tid >> 5;
        int p0 = pT * 32, c0 = cT * 32;
        const float* ib = x + (size_t)b * 128 * HWSZ;
        float* ob = g_xt + (size_t)b * HWSZ * 128;
        #pragma unroll
        for (int i = 0; i < 4; ++i)
            t[ty + 8 * i][tx] = ib[(size_t)(c0 + ty + 8 * i) * HWSZ + p0 + tx];
        __syncthreads();
        #pragma unroll
        for (int i = 0; i < 4; ++i)
            ob[(size_t)(p0 + ty + 8 * i) * 128 + c0 + tx] = t[tx][ty + 8 * i];
        return;
    }
    blk -= R1B;
    if (blk < R2B) {                                // cond -> NHWC bf16 hi/lo pad C1P
        __shared__ float t[32][33];
        int ct = blk % 9, pt = (blk / 9) & 511, b = blk / 4608;
        int tx = tid & 31, ty = tid >> 5;
        int c0 = ct * 32, p0 = pt * 32;
        #pragma unroll
        for (int i = 0; i < 4; ++i) {
            int c = c0 + ty + 8 * i;
            t[ty + 8 * i][tx] = (c < 261) ? cond[((size_t)(b * 261 + c) << 14) + p0 + tx] : 0.f;
        }
        __syncthreads();
        #pragma unroll
        for (int i = 0; i < 4; ++i) {
            float v = t[tx][ty + 8 * i];
            bf16 h = __float2bfloat16(v);
            size_t o = ((size_t)(b << 14) + p0 + ty + 8 * i) * C1P + c0 + tx;
            g_ch[o] = h;
            g_cl[o] = __float2bfloat16(v - __bfloat162float(h));
        }
        return;
    }
    blk -= R2B;
    if (blk < W1BLK) { wtile_one(blk * 256 + tid, w1, g_wt1, 261, 128, 128); return; }
    blk -= W1BLK;
    if (blk < W2BLK) { wtile_one(blk * 256 + tid, w2, g_wt2, 128, 128, 128); return; }
    blk -= W2BLK;
    if (blk < W2BLK) { wtile_one(blk * 256 + tid, w3, g_wt3, 128, 128, 128); return; }
    blk -= W2BLK;
    if (blk < W2BLK) { wtile_one(blk * 256 + tid, wd, g_wtd, 128, 128, 128); return; }
    blk -= W2BLK;
    if (blk < W4BLK) { wtile_one(blk * 256 + tid, w4, g_wt4, 128, 27, 32); return; }
    if (tid < 32) g_b4p[tid] = (tid < 27) ? b4[tid] : 0.f;
}

// ---------------- conv3x3 via mma.sync bf16 (hi/lo split, 3 combos) ----------------
template <int NCO, int NCH, int CINP, int MODE>
__global__ __launch_bounds__(256, 2)
void conv_mma(const bf16* __restrict__ ih, const bf16* __restrict__ il,
              const bf16* __restrict__ wt, const float* __restrict__ bias,
              bf16* __restrict__ oh, bf16* __restrict__ ol, float* __restrict__ of) {
    constexpr int NWN = (NCO == 128) ? 2 : 1;
    constexpr int NM  = (NCO == 128) ? 2 : 1;
    constexpr int NN  = (NCO == 128) ? 8 : 4;
    constexpr int ASP = 3 * 132 * 48;
    constexpr int BSP = NCO * 48;
    constexpr int BBUF = 2 * BSP;

    extern __shared__ char sm[];
    __shared__ float s_bias[NCO];
    char* As = sm;
    char* Bs = sm + 2 * ASP;

    const int tid = threadIdx.x, wid = tid >> 5, lane = tid & 31;
    const int y0 = blockIdx.x, b = blockIdx.y;
    const size_t bofs = (size_t)b * HWSZ;
    if (tid < NCO) s_bias[tid] = bias[tid];

    const int wm = (wid / NWN) * (NM * 16);
    const int wn = (wid % NWN) * (NN * 8);
    const uint32_t Asb = s2u(sm);
    const uint32_t Bsb = Asb + 2 * ASP;

    float d[NM][NN][4];
    #pragma unroll
    for (int m = 0; m < NM; ++m)
        #pragma unroll
        for (int j = 0; j < NN; ++j)
            #pragma unroll
            for (int q = 0; q < 4; ++q) d[m][j][q] = 0.f;

    auto stageB = [&](int ch, int tap, int buf) {
        const uint4* src = (const uint4*)(wt + (size_t)((ch * 9 + tap) * 2) * NCO * 24);
        uint4* dst = (uint4*)(Bs + buf * BBUF);
        #pragma unroll
        for (int i = tid; i < NCO * 6; i += 256) dst[i] = src[i];
    };

    for (int ch = 0; ch < NCH; ++ch) {
        for (int e = tid; e < 1584; e += 256) {
            int sp = e / 792, f = e - sp * 792;
            int half = f & 1, rp = f >> 1;
            int r = rp / 132, px = rp - r * 132;
            int iy = y0 + r - 1, ix = px - 1;
            uint4 v = make_uint4(0, 0, 0, 0);
            if ((unsigned)iy < 128u && (unsigned)ix < 128u)
                v = *(const uint4*)((sp ? il : ih) +
                    (bofs + (size_t)iy * WW + ix) * CINP + ch * 16 + half * 8);
            *(uint4*)(As + sp * ASP + rp * 48 + half * 16) = v;
        }
        stageB(ch, 0, 0);
        __syncthreads();

        for (int tap = 0; tap < 9; ++tap) {
            if (tap < 8) stageB(ch, tap + 1, (tap + 1) & 1);

            const int dy = tap / 3 - 1, dx = tap % 3 - 1;
            uint32_t ah[NM][4], al[NM][4];
            const int arow = (dy + 1) * 132;
            #pragma unroll
            for (int m = 0; m < NM; ++m) {
                uint32_t aa = Asb + (uint32_t)(arow + wm + m * 16 + dx + 1 + (lane & 15)) * 48
                            + (lane >> 4) * 16;
                ldsm4(ah[m], aa);
                ldsm4(al[m], aa + ASP);
            }
            const uint32_t bq = Bsb + (tap & 1) * BBUF;
            const uint32_t boff = (uint32_t)((lane & 7) + ((lane >> 4) << 3)) * 48
                                + ((lane >> 3) & 1) * 16;
            uint32_t bb[NN / 2][4];
            #pragma unroll
            for (int nt = 0; nt < NN / 2; ++nt)
                ldsm4(bb[nt], bq + (uint32_t)(wn + nt * 16) * 48 + boff);
            #pragma unroll
            for (int m = 0; m < NM; ++m)
                #pragma unroll
                for (int j = 0; j < NN; ++j) {
                    uint32_t b0 = bb[j >> 1][(j & 1) * 2], b1 = bb[j >> 1][(j & 1) * 2 + 1];
                    mma16816(d[m][j], ah[m], b0, b1);
                    mma16816(d[m][j], al[m], b0, b1);
                }
            #pragma unroll
            for (int nt = 0; nt < NN / 2; ++nt)
                ldsm4(bb[nt], bq + BSP + (uint32_t)(wn + nt * 16) * 48 + boff);
            #pragma unroll
            for (int m = 0; m < NM; ++m)
                #pragma unroll
                for (int j = 0; j < NN; ++j)
                    mma16816(d[m][j], ah[m], bb[j >> 1][(j & 1) * 2], bb[j >> 1][(j & 1) * 2 + 1]);
            __syncthreads();
        }
    }

    const int g = lane >> 2, tig = lane & 3;
    #pragma unroll
    for (int m = 0; m < NM; ++m) {
        #pragma unroll
        for (int j = 0; j < NN; ++j) {
            int col = wn + j * 8 + 2 * tig;
            float blo = s_bias[col], bhi = s_bias[col + 1];
            #pragma unroll
            for (int hrow = 0; hrow < 2; ++hrow) {
                int xr = wm + m * 16 + g + hrow * 8;
                float v0 = d[m][j][hrow * 2] + blo;
                float v1 = d[m][j][hrow * 2 + 1] + bhi;
                size_t pix = bofs + (size_t)y0 * WW + xr;
                if (MODE == 0) {
                    v0 = v0 >= 0.f ? v0 : 0.1f * v0;
                    v1 = v1 >= 0.f ? v1 : 0.1f * v1;
                    bf16 h0 = __float2bfloat16(v0), h1 = __float2bfloat16(v1);
                    __nv_bfloat162 hv; hv.x = h0; hv.y = h1;
                    __nv_bfloat162 lv;
                    lv.x = __float2bfloat16(v0 - __bfloat162float(h0));
                    lv.y = __float2bfloat16(v1 - __bfloat162float(h1));
                    *(__nv_bfloat162*)(oh + pix * 128 + col) = hv;
                    *(__nv_bfloat162*)(ol + pix * 128 + col) = lv;
                } else {
                    *(float2*)(of + pix * 32 + col) = make_float2(v0, v1);
                }
            }
        }
    }
}

// ---------------- deformable conv via mma.sync (sampled im2col GEMM) ----------------
// Block: 128 px (one row) x 128 co. K = 8 ci-chunks x 9 taps, 72 stages.
// Stage: bilinear-sample 128px x 16ci fp32 -> bf16 hi/lo A tile (48B stride);
// B tiles pre-tiled (g_wtd). Same frag addressing as conv_mma. Output NCHW fp32.
// smem: sw float4[1152] | sidx int4[1152] | A[2 buf][2 sp][6144] | B[2 buf][2 sp][6144]
#define DM_SMEM (18432 + 18432 + 24576 + 24576)

__global__ __launch_bounds__(256, 2)
void deform_mma(const float* __restrict__ xt, const float* __restrict__ head,
                const float* __restrict__ flow, const bf16* __restrict__ wtd,
                const float* __restrict__ bias, float* __restrict__ out) {
    extern __shared__ char sm[];
    float4* sw = (float4*)sm;
    int4*  sidx = (int4*)(sm + 18432);
    char* As = sm + 36864;
    char* Bs = sm + 36864 + 24576;
    __shared__ float s_bias[128];

    const int tid = threadIdx.x, wid = tid >> 5, lane = tid & 31;
    const int y0 = blockIdx.x, b = blockIdx.y;
    if (tid < 128) s_bias[tid] = bias[tid];

    // phase 0: sampling params for 9 taps x 128 px of this row
    for (int e = tid; e < 1152; e += 256) {
        int k = e >> 7, px = e & 127;
        int pix = y0 * WW + px;
        const float* hb = head + ((size_t)b * HWSZ + pix) * 32;
        float dyr = hb[2 * k], dxr = hb[2 * k + 1], mr = hb[18 + k];
        const float* fb = flow + (size_t)b * 2 * HWSZ + pix;
        float fx = fb[0], fy = fb[HWSZ];
        float py = (float)(y0 - 1 + k / 3) + 3.0f * tanhf(dyr) + fy;
        float pxf = (float)(px - 1 + (k - 3 * (k / 3))) + 3.0f * tanhf(dxr) + fx;
        float m = 1.0f / (1.0f + __expf(-mr));
        float fy0 = floorf(py), fx0 = floorf(pxf);
        float ay = py - fy0, ax = pxf - fx0;
        int iy0 = (int)fy0, ix0 = (int)fx0;
        int iy1 = iy0 + 1, ix1 = ix0 + 1;
        float vy0 = (iy0 >= 0 && iy0 < HH) ? m : 0.f;
        float vy1 = (iy1 >= 0 && iy1 < HH) ? m : 0.f;
        float vx0 = (ix0 >= 0 && ix0 < WW) ? 1.f : 0.f;
        float vx1 = (ix1 >= 0 && ix1 < WW) ? 1.f : 0.f;
        sw[e] = make_float4((1.f - ay) * (1.f - ax) * vy0 * vx0,
                            (1.f - ay) * ax * vy0 * vx1,
                            ay * (1.f - ax) * vy1 * vx0,
                            ay * ax * vy1 * vx1);
        int cy0 = min(max(iy0, 0), HH - 1), cy1 = min(max(iy1, 0), HH - 1);
        int cx0 = min(max(ix0, 0), WW - 1), cx1 = min(max(ix1, 0), WW - 1);
        sidx[e] = make_int4(cy0 * WW + cx0, cy0 * WW + cx1, cy1 * WW + cx0, cy1 * WW + cx1);
    }

    const float* xb = xt + (size_t)b * HWSZ * 128;
    const uint32_t Asb = s2u(sm) + 36864;
    const uint32_t Bsb = Asb + 24576;
    const int wm = (wid >> 1) * 32;       // 4 warp-rows of 32 px
    const int wn = (wid & 1) * 64;        // 2 warp-cols of 64 co

    float d[2][8][4];
    #pragma unroll
    for (int m = 0; m < 2; ++m)
        #pragma unroll
        for (int j = 0; j < 8; ++j)
            #pragma unroll
            for (int q = 0; q < 4; ++q) d[m][j][q] = 0.f;

    auto stage = [&](int ch, int tap, int buf) {
        // B: straight copy of pre-tiled weights (2 splits x 128co x 48B)
        const uint4* src = (const uint4*)(wtd + (size_t)((ch * 9 + tap) * 2) * 128 * 24);
        uint4* dst = (uint4*)(Bs + buf * 12288);
        #pragma unroll
        for (int i = tid; i < 768; i += 256) dst[i] = src[i];
        // A: sample 128 px x 16 ci; thread = (px, 8-ci half)
        int px = tid & 127, half = tid >> 7;
        int e = tap * 128 + px;
        float4 wv = sw[e];
        int4 iv = sidx[e];
        int c0 = ch * 16 + half * 8;
        bf16 hv[8], lv[8];
        #pragma unroll
        for (int u = 0; u < 2; ++u) {
            float4 c00 = __ldg((const float4*)(xb + (size_t)iv.x * 128 + c0 + 4 * u));
            float4 c01 = __ldg((const float4*)(xb + (size_t)iv.y * 128 + c0 + 4 * u));
            float4 c10 = __ldg((const float4*)(xb + (size_t)iv.z * 128 + c0 + 4 * u));
            float4 c11 = __ldg((const float4*)(xb + (size_t)iv.w * 128 + c0 + 4 * u));
            #pragma unroll
            for (int q = 0; q < 4; ++q) {
                float v = wv.x * (&c00.x)[q] + wv.y * (&c01.x)[q]
                        + wv.z * (&c10.x)[q] + wv.w * (&c11.x)[q];
                bf16 h = __float2bfloat16(v);
                hv[4 * u + q] = h;
                lv[4 * u + q] = __float2bfloat16(v - __bfloat162float(h));
            }
        }
        char* ab = As + buf * 12288;
        *(uint4*)(ab + px * 48 + half * 16) = *(uint4*)hv;
        *(uint4*)(ab + 6144 + px * 48 + half * 16) = *(uint4*)lv;
    };

    __syncthreads();       // params visible
    stage(0, 0, 0);
    __syncthreads();

    for (int s = 0; s < 72; ++s) {
        const int cur = s & 1;
        if (s + 1 < 72) stage((s + 1) / 9, (s + 1) % 9, cur ^ 1);

        uint32_t ah[2][4], al[2][4];
        #pragma unroll
        for (int m = 0; m < 2; ++m) {
            uint32_t aa = Asb + cur * 12288 + (uint32_t)(wm + m * 16 + (lane & 15)) * 48
                        + (lane >> 4) * 16;
            ldsm4(ah[m], aa);
            ldsm4(al[m], aa + 6144);
        }
        const uint32_t bq = Bsb + cur * 12288;
        const uint32_t boff = (uint32_t)((lane & 7) + ((lane >> 4) << 3)) * 48
                            + ((lane >> 3) & 1) * 16;
        uint32_t bb[4][4];
        #pragma unroll
        for (int nt = 0; nt < 4; ++nt)
            ldsm4(bb[nt], bq + (uint32_t)(wn + nt * 16) * 48 + boff);
        #pragma unroll
        for (int m = 0; m < 2; ++m)
            #pragma unroll
            for (int j = 0; j < 8; ++j) {
                uint32_t b0 = bb[j >> 1][(j & 1) * 2], b1 = bb[j >> 1][(j & 1) * 2 + 1];
                mma16816(d[m][j], ah[m], b0, b1);   // ah*bh
                mma16816(d[m][j], al[m], b0, b1);   // al*bh
            }
        #pragma unroll
        for (int nt = 0; nt < 4; ++nt)
            ldsm4(bb[nt], bq + 6144 + (uint32_t)(wn + nt * 16) * 48 + boff);
        #pragma unroll
        for (int m = 0; m < 2; ++m)
            #pragma unroll
            for (int j = 0; j < 8; ++j)
                mma16816(d[m][j], ah[m], bb[j >> 1][(j & 1) * 2], bb[j >> 1][(j & 1) * 2 + 1]); // ah*bl
        __syncthreads();
    }

    // epilogue: NCHW fp32 to d_out
    const int g = lane >> 2, tig = lane & 3;
    #pragma unroll
    for (int m = 0; m < 2; ++m) {
        #pragma unroll
        for (int j = 0; j < 8; ++j) {
            int col = wn + j * 8 + 2 * tig;
            float blo = s_bias[col], bhi = s_bias[col + 1];
            #pragma unroll
            for (int hrow = 0; hrow < 2; ++hrow) {
                int px = wm + m * 16 + g + hrow * 8;
                float v0 = d[m][j][hrow * 2] + blo;
                float v1 = d[m][j][hrow * 2 + 1] + bhi;
                float* o = out + (((size_t)(b * 128 + col) * HH + y0) * WW + px);
                o[0] = v0;
                o[HWSZ] = v1;
            }
        }
    }
}

// ---------------- launcher ----------------
extern "C" void kernel_launch(void* const* d_in, const int* in_sizes, int n_in,
                              void* d_out, int out_size) {
    const float* x    = (const float*)d_in[0];
    const float* cond = (const float*)d_in[1];
    const float* flow = (const float*)d_in[2];
    const float* w1 = (const float*)d_in[3];
    const float* b1 = (const float*)d_in[4];
    const float* w2 = (const float*)d_in[5];
    const float* b2 = (const float*)d_in[6];
    const float* w3 = (const float*)d_in[7];
    const float* b3 = (const float*)d_in[8];
    const float* w4 = (const float*)d_in[9];
    const float* b4 = (const float*)d_in[10];
    const float* wd = (const float*)d_in[11];
    const float* bd = (const float*)d_in[12];
    float* out = (float*)d_out;

    float *xtp, *headp, *b4p;
    bf16 *chp, *clp, *ahp, *alp, *bhp, *blp, *wt1, *wt2, *wt3, *wt4, *wtd;
    cudaGetSymbolAddress((void**)&xtp, g_xt);
    cudaGetSymbolAddress((void**)&chp, g_ch);
    cudaGetSymbolAddress((void**)&clp, g_cl);
    cudaGetSymbolAddress((void**)&ahp, g_ah);
    cudaGetSymbolAddress((void**)&alp, g_al);
    cudaGetSymbolAddress((void**)&bhp, g_bh);
    cudaGetSymbolAddress((void**)&blp, g_bl);
    cudaGetSymbolAddress((void**)&headp, g_head);
    cudaGetSymbolAddress((void**)&wt1, g_wt1);
    cudaGetSymbolAddress((void**)&wt2, g_wt2);
    cudaGetSymbolAddress((void**)&wt3, g_wt3);
    cudaGetSymbolAddress((void**)&wt4, g_wt4);
    cudaGetSymbolAddress((void**)&wtd, g_wtd);
    cudaGetSymbolAddress((void**)&b4p, g_b4p);

    const int SM128 = 2 * (3 * 132 * 48) + 2 * 2 * 128 * 48;   // 62592
    const int SM32  = 2 * (3 * 132 * 48) + 2 * 2 * 32 * 48;    // 44160
    cudaFuncSetAttribute(conv_mma<128, 18, C1P, 0>, cudaFuncAttributeMaxDynamicSharedMemorySize, SM128);
    cudaFuncSetAttribute(conv_mma<128, 8, 128, 0>,  cudaFuncAttributeMaxDynamicSharedMemorySize, SM128);
    cudaFuncSetAttribute(conv_mma<32, 8, 128, 1>,   cudaFuncAttributeMaxDynamicSharedMemorySize, SM32);
    cudaFuncSetAttribute(deform_mma, cudaFuncAttributeMaxDynamicSharedMemorySize, DM_SMEM);

    prep_kernel<<<PREP_NB, 256>>>(x, cond, w1, w2, w3, w4, wd, b4);

    dim3 gc(128, BB);
    conv_mma<128, 18, C1P, 0><<<gc, 256, SM128>>>(chp, clp, wt1, b1, ahp, alp, nullptr);
    conv_mma<128, 8, 128, 0><<<gc, 256, SM128>>>(ahp, alp, wt2, b2, bhp, blp, nullptr);
    conv_mma<128, 8, 128, 0><<<gc, 256, SM128>>>(bhp, blp, wt3, b3, ahp, alp, nullptr);
    conv_mma<32, 8, 128, 1><<<gc, 256, SM32>>>(ahp, alp, wt4, b4p, nullptr, nullptr, headp);

    deform_mma<<<gc, 256, DM_SMEM>>>(xtp, headp, flow, wtd, bd, out);
}

// round 17
// speedup vs baseline: 2.3262x; 1.1433x over previous
#include <cuda_runtime.h>
#include <cuda_bf16.h>
#include <cstdint>
#include <math.h>

#define HH 128
#define WW 128
#define HWSZ (HH*WW)
#define BB 4

typedef unsigned long long ull;
typedef __nv_bfloat16 bf16;

// ---------------- HMMA helpers (baseline PTX, sm_80+) ----------------
__device__ __forceinline__ uint32_t s2u(const void* p) {
    uint32_t a;
    asm("{ .reg .u64 t; cvta.to.shared.u64 t, %1; cvt.u32.u64 %0, t; }" : "=r"(a) : "l"(p));
    return a;
}
__device__ __forceinline__ void ldsm4(uint32_t* r, uint32_t addr) {
    asm volatile("ldmatrix.sync.aligned.m8n8.x4.shared.b16 {%0,%1,%2,%3}, [%4];"
        : "=r"(r[0]), "=r"(r[1]), "=r"(r[2]), "=r"(r[3]) : "r"(addr));
}
__device__ __forceinline__ void mma16816(float* d, const uint32_t* a, uint32_t b0, uint32_t b1) {
    asm volatile("mma.sync.aligned.m16n8k16.row.col.f32.bf16.bf16.f32 "
        "{%0,%1,%2,%3}, {%4,%5,%6,%7}, {%8,%9}, {%0,%1,%2,%3};"
        : "+f"(d[0]), "+f"(d[1]), "+f"(d[2]), "+f"(d[3])
        : "r"(a[0]), "r"(a[1]), "r"(a[2]), "r"(a[3]), "r"(b0), "r"(b1));
}

// ---------------- scratch globals ----------------
#define C1P 288                       // conv1 input channels padded (261 -> 288)
__device__ __align__(16) float g_xt[BB * 128 * HWSZ];       // x NHWC fp32 (deform gather)
__device__ __align__(16) bf16  g_ch[BB * HWSZ * C1P];       // cond NHWC hi
__device__ __align__(16) bf16  g_cl[BB * HWSZ * C1P];       // cond NHWC lo
__device__ __align__(16) bf16  g_ah[BB * HWSZ * 128], g_al[BB * HWSZ * 128];
__device__ __align__(16) bf16  g_bh[BB * HWSZ * 128], g_bl[BB * HWSZ * 128];
__device__ __align__(16) float g_head[BB * HWSZ * 32];      // head NHWC fp32 (27 used)
// weight tiles: [ch][tap][sp][co][24ci] bf16 (16 used + 8 pad per row)
__device__ __align__(16) bf16  g_wt1[18*9*2*128*24];
__device__ __align__(16) bf16  g_wt2[8*9*2*128*24];
__device__ __align__(16) bf16  g_wt3[8*9*2*128*24];
__device__ __align__(16) bf16  g_wt4[8*9*2*32*24];
__device__ __align__(16) bf16  g_wtd[8*9*2*128*24];         // deform weights, same tile format
__device__ float g_b4p[32];

// ---------------- prep ----------------
#define R1B 8192
#define R2B (4*512*9)
#define W1E (18*9*2*128*24)
#define W2E (8*9*2*128*24)
#define W4E (8*9*2*32*24)
#define W1BLK (W1E/256)
#define W2BLK (W2E/256)
#define W4BLK (W4E/256)
#define PREP_NB (R1B + R2B + W1BLK + 3*W2BLK + W4BLK + 1)

__device__ __forceinline__ void wtile_one(int i, const float* __restrict__ w,
                                          bf16* __restrict__ dst, int Cin, int Cout, int NCO) {
    int ci = i % 24; int t = i / 24;
    int co = t % NCO; t /= NCO;
    int sp = t & 1; t >>= 1;
    int tap = t % 9; int ch = t / 9;
    int cig = ch * 16 + ci;
    float v = (ci < 16 && cig < Cin && co < Cout) ? w[((size_t)co * Cin + cig) * 9 + tap] : 0.f;
    bf16 h = __float2bfloat16(v);
    dst[i] = sp ? __float2bfloat16(v - __bfloat162float(h)) : h;
}

__global__ void prep_kernel(const float* __restrict__ x, const float* __restrict__ cond,
                            const float* __restrict__ w1, const float* __restrict__ w2,
                            const float* __restrict__ w3, const float* __restrict__ w4,
                            const float* __restrict__ wd, const float* __restrict__ b4) {
    int blk = blockIdx.x, tid = threadIdx.x;
    if (blk < R1B) {                                // x NCHW -> NHWC fp32
        __shared__ float t[32][33];
        int pT = blk & 511, cT = (blk >> 9) & 3, b = blk >> 11;
        int tx = tid & 31, ty = tid >> 5;
        int p0 = pT * 32, c0 = cT * 32;
        const float* ib = x + (size_t)b * 128 * HWSZ;
        float* ob = g_xt + (size_t)b * HWSZ * 128;
        #pragma unroll
        for (int i = 0; i < 4; ++i)
            t[ty + 8 * i][tx] = ib[(size_t)(c0 + ty + 8 * i) * HWSZ + p0 + tx];
        __syncthreads();
        #pragma unroll
        for (int i = 0; i < 4; ++i)
            ob[(size_t)(p0 + ty + 8 * i) * 128 + c0 + tx] = t[tx][ty + 8 * i];
        return;
    }
    blk -= R1B;
    if (blk < R2B) {                                // cond -> NHWC bf16 hi/lo pad C1P
        __shared__ float t[32][33];
        int ct = blk % 9, pt = (blk / 9) & 511, b = blk / 4608;
        int tx = tid & 31, ty = tid >> 5;
        int c0 = ct * 32, p0 = pt * 32;
        #pragma unroll
        for (int i = 0; i < 4; ++i) {
            int c = c0 + ty + 8 * i;
            t[ty + 8 * i][tx] = (c < 261) ? cond[((size_t)(b * 261 + c) << 14) + p0 + tx] : 0.f;
        }
        __syncthreads();
        #pragma unroll
        for (int i = 0; i < 4; ++i) {
            float v = t[tx][ty + 8 * i];
            bf16 h = __float2bfloat16(v);
            size_t o = ((size_t)(b << 14) + p0 + ty + 8 * i) * C1P + c0 + tx;
            g_ch[o] = h;
            g_cl[o] = __float2bfloat16(v - __bfloat162float(h));
        }
        return;
    }
    blk -= R2B;
    if (blk < W1BLK) { wtile_one(blk * 256 + tid, w1, g_wt1, 261, 128, 128); return; }
    blk -= W1BLK;
    if (blk < W2BLK) { wtile_one(blk * 256 + tid, w2, g_wt2, 128, 128, 128); return; }
    blk -= W2BLK;
    if (blk < W2BLK) { wtile_one(blk * 256 + tid, w3, g_wt3, 128, 128, 128); return; }
    blk -= W2BLK;
    if (blk < W2BLK) { wtile_one(blk * 256 + tid, wd, g_wtd, 128, 128, 128); return; }
    blk -= W2BLK;
    if (blk < W4BLK) { wtile_one(blk * 256 + tid, w4, g_wt4, 128, 27, 32); return; }
    if (tid < 32) g_b4p[tid] = (tid < 27) ? b4[tid] : 0.f;
}

// ---------------- conv3x3 via mma.sync bf16 (hi/lo split, 3 combos) ----------------
template <int NCO, int NCH, int CINP, int MODE>
__global__ __launch_bounds__(256, 2)
void conv_mma(const bf16* __restrict__ ih, const bf16* __restrict__ il,
              const bf16* __restrict__ wt, const float* __restrict__ bias,
              bf16* __restrict__ oh, bf16* __restrict__ ol, float* __restrict__ of) {
    constexpr int NWN = (NCO == 128) ? 2 : 1;
    constexpr int NM  = (NCO == 128) ? 2 : 1;
    constexpr int NN  = (NCO == 128) ? 8 : 4;
    constexpr int ASP = 3 * 132 * 48;
    constexpr int BSP = NCO * 48;
    constexpr int BBUF = 2 * BSP;

    extern __shared__ char sm[];
    __shared__ float s_bias[NCO];
    char* As = sm;
    char* Bs = sm + 2 * ASP;

    const int tid = threadIdx.x, wid = tid >> 5, lane = tid & 31;
    const int y0 = blockIdx.x, b = blockIdx.y;
    const size_t bofs = (size_t)b * HWSZ;
    if (tid < NCO) s_bias[tid] = bias[tid];

    const int wm = (wid / NWN) * (NM * 16);
    const int wn = (wid % NWN) * (NN * 8);
    const uint32_t Asb = s2u(sm);
    const uint32_t Bsb = Asb + 2 * ASP;

    float d[NM][NN][4];
    #pragma unroll
    for (int m = 0; m < NM; ++m)
        #pragma unroll
        for (int j = 0; j < NN; ++j)
            #pragma unroll
            for (int q = 0; q < 4; ++q) d[m][j][q] = 0.f;

    auto stageB = [&](int ch, int tap, int buf) {
        const uint4* src = (const uint4*)(wt + (size_t)((ch * 9 + tap) * 2) * NCO * 24);
        uint4* dst = (uint4*)(Bs + buf * BBUF);
        #pragma unroll
        for (int i = tid; i < NCO * 6; i += 256) dst[i] = src[i];
    };

    for (int ch = 0; ch < NCH; ++ch) {
        for (int e = tid; e < 1584; e += 256) {
            int sp = e / 792, f = e - sp * 792;
            int half = f & 1, rp = f >> 1;
            int r = rp / 132, px = rp - r * 132;
            int iy = y0 + r - 1, ix = px - 1;
            uint4 v = make_uint4(0, 0, 0, 0);
            if ((unsigned)iy < 128u && (unsigned)ix < 128u)
                v = *(const uint4*)((sp ? il : ih) +
                    (bofs + (size_t)iy * WW + ix) * CINP + ch * 16 + half * 8);
            *(uint4*)(As + sp * ASP + rp * 48 + half * 16) = v;
        }
        stageB(ch, 0, 0);
        __syncthreads();

        for (int tap = 0; tap < 9; ++tap) {
            if (tap < 8) stageB(ch, tap + 1, (tap + 1) & 1);

            const int dy = tap / 3 - 1, dx = tap % 3 - 1;
            uint32_t ah[NM][4], al[NM][4];
            const int arow = (dy + 1) * 132;
            #pragma unroll
            for (int m = 0; m < NM; ++m) {
                uint32_t aa = Asb + (uint32_t)(arow + wm + m * 16 + dx + 1 + (lane & 15)) * 48
                            + (lane >> 4) * 16;
                ldsm4(ah[m], aa);
                ldsm4(al[m], aa + ASP);
            }
            const uint32_t bq = Bsb + (tap & 1) * BBUF;
            const uint32_t boff = (uint32_t)((lane & 7) + ((lane >> 4) << 3)) * 48
                                + ((lane >> 3) & 1) * 16;
            uint32_t bb[NN / 2][4];
            #pragma unroll
            for (int nt = 0; nt < NN / 2; ++nt)
                ldsm4(bb[nt], bq + (uint32_t)(wn + nt * 16) * 48 + boff);
            #pragma unroll
            for (int m = 0; m < NM; ++m)
                #pragma unroll
                for (int j = 0; j < NN; ++j) {
                    uint32_t b0 = bb[j >> 1][(j & 1) * 2], b1 = bb[j >> 1][(j & 1) * 2 + 1];
                    mma16816(d[m][j], ah[m], b0, b1);
                    mma16816(d[m][j], al[m], b0, b1);
                }
            #pragma unroll
            for (int nt = 0; nt < NN / 2; ++nt)
                ldsm4(bb[nt], bq + BSP + (uint32_t)(wn + nt * 16) * 48 + boff);
            #pragma unroll
            for (int m = 0; m < NM; ++m)
                #pragma unroll
                for (int j = 0; j < NN; ++j)
                    mma16816(d[m][j], ah[m], bb[j >> 1][(j & 1) * 2], bb[j >> 1][(j & 1) * 2 + 1]);
            __syncthreads();
        }
    }

    const int g = lane >> 2, tig = lane & 3;
    #pragma unroll
    for (int m = 0; m < NM; ++m) {
        #pragma unroll
        for (int j = 0; j < NN; ++j) {
            int col = wn + j * 8 + 2 * tig;
            float blo = s_bias[col], bhi = s_bias[col + 1];
            #pragma unroll
            for (int hrow = 0; hrow < 2; ++hrow) {
                int xr = wm + m * 16 + g + hrow * 8;
                float v0 = d[m][j][hrow * 2] + blo;
                float v1 = d[m][j][hrow * 2 + 1] + bhi;
                size_t pix = bofs + (size_t)y0 * WW + xr;
                if (MODE == 0) {
                    v0 = v0 >= 0.f ? v0 : 0.1f * v0;
                    v1 = v1 >= 0.f ? v1 : 0.1f * v1;
                    bf16 h0 = __float2bfloat16(v0), h1 = __float2bfloat16(v1);
                    __nv_bfloat162 hv; hv.x = h0; hv.y = h1;
                    __nv_bfloat162 lv;
                    lv.x = __float2bfloat16(v0 - __bfloat162float(h0));
                    lv.y = __float2bfloat16(v1 - __bfloat162float(h1));
                    *(__nv_bfloat162*)(oh + pix * 128 + col) = hv;
                    *(__nv_bfloat162*)(ol + pix * 128 + col) = lv;
                } else {
                    *(float2*)(of + pix * 32 + col) = make_float2(v0, v1);
                }
            }
        }
    }
}

// ---------------- deformable conv via mma.sync (sampled im2col GEMM) ----------------
// Block: 128 px (one row) x 128 co. K = 8 ci-chunks x 9 taps, 72 stages.
// Gather lane map: lane = (px_local<<2)|ci_quad -> 4 consecutive lanes read 64B
// contiguous of the SAME (pixel, corner) => ~8 wavefronts/LDG instead of ~32.
// smem: sw float4[1152] | sidx int4[1152] | A[2 buf][2 sp][6144] | B[2 buf][2 sp][6144]
#define DM_SMEM (18432 + 18432 + 24576 + 24576)

__global__ __launch_bounds__(256, 2)
void deform_mma(const float* __restrict__ xt, const float* __restrict__ head,
                const float* __restrict__ flow, const bf16* __restrict__ wtd,
                const float* __restrict__ bias, float* __restrict__ out) {
    extern __shared__ char sm[];
    float4* sw = (float4*)sm;
    int4*  sidx = (int4*)(sm + 18432);
    char* As = sm + 36864;
    char* Bs = sm + 36864 + 24576;
    __shared__ float s_bias[128];

    const int tid = threadIdx.x, wid = tid >> 5, lane = tid & 31;
    const int y0 = blockIdx.x, b = blockIdx.y;
    if (tid < 128) s_bias[tid] = bias[tid];

    // phase 0: sampling params for 9 taps x 128 px of this row
    for (int e = tid; e < 1152; e += 256) {
        int k = e >> 7, px = e & 127;
        int pix = y0 * WW + px;
        const float* hb = head + ((size_t)b * HWSZ + pix) * 32;
        float dyr = hb[2 * k], dxr = hb[2 * k + 1], mr = hb[18 + k];
        const float* fb = flow + (size_t)b * 2 * HWSZ + pix;
        float fx = fb[0], fy = fb[HWSZ];
        float py = (float)(y0 - 1 + k / 3) + 3.0f * tanhf(dyr) + fy;
        float pxf = (float)(px - 1 + (k - 3 * (k / 3))) + 3.0f * tanhf(dxr) + fx;
        float m = 1.0f / (1.0f + __expf(-mr));
        float fy0 = floorf(py), fx0 = floorf(pxf);
        float ay = py - fy0, ax = pxf - fx0;
        int iy0 = (int)fy0, ix0 = (int)fx0;
        int iy1 = iy0 + 1, ix1 = ix0 + 1;
        float vy0 = (iy0 >= 0 && iy0 < HH) ? m : 0.f;
        float vy1 = (iy1 >= 0 && iy1 < HH) ? m : 0.f;
        float vx0 = (ix0 >= 0 && ix0 < WW) ? 1.f : 0.f;
        float vx1 = (ix1 >= 0 && ix1 < WW) ? 1.f : 0.f;
        sw[e] = make_float4((1.f - ay) * (1.f - ax) * vy0 * vx0,
                            (1.f - ay) * ax * vy0 * vx1,
                            ay * (1.f - ax) * vy1 * vx0,
                            ay * ax * vy1 * vx1);
        int cy0 = min(max(iy0, 0), HH - 1), cy1 = min(max(iy1, 0), HH - 1);
        int cx0 = min(max(ix0, 0), WW - 1), cx1 = min(max(ix1, 0), WW - 1);
        sidx[e] = make_int4(cy0 * WW + cx0, cy0 * WW + cx1, cy1 * WW + cx0, cy1 * WW + cx1);
    }

    const float* xb = xt + (size_t)b * HWSZ * 128;
    const uint32_t Asb = s2u(sm) + 36864;
    const uint32_t Bsb = Asb + 24576;
    const int wm = (wid >> 1) * 32;       // 4 warp-rows of 32 px
    const int wn = (wid & 1) * 64;        // 2 warp-cols of 64 co
    const int pxl = lane >> 2, ciq = lane & 3;

    float d[2][8][4];
    #pragma unroll
    for (int m = 0; m < 2; ++m)
        #pragma unroll
        for (int j = 0; j < 8; ++j)
            #pragma unroll
            for (int q = 0; q < 4; ++q) d[m][j][q] = 0.f;

    auto stage = [&](int ch, int tap, int buf) {
        // B: straight copy of pre-tiled weights (2 splits x 128co x 48B)
        const uint4* src = (const uint4*)(wtd + (size_t)((ch * 9 + tap) * 2) * 128 * 24);
        uint4* dst = (uint4*)(Bs + buf * 12288);
        #pragma unroll
        for (int i = tid; i < 768; i += 256) dst[i] = src[i];
        // A: sample 128 px x 16 ci; warp covers 16 px, lane = (px_local, ci_quad)
        char* ab = As + buf * 12288;
        const float* base = xb + ch * 16 + ciq * 4;
        #pragma unroll
        for (int u = 0; u < 2; ++u) {
            int px = wid * 16 + u * 8 + pxl;
            int e = tap * 128 + px;
            float4 wv = sw[e];
            int4 iv = sidx[e];
            float4 c00 = __ldg((const float4*)(base + (size_t)iv.x * 128));
            float4 c01 = __ldg((const float4*)(base + (size_t)iv.y * 128));
            float4 c10 = __ldg((const float4*)(base + (size_t)iv.z * 128));
            float4 c11 = __ldg((const float4*)(base + (size_t)iv.w * 128));
            bf16 hv[4], lv[4];
            #pragma unroll
            for (int q = 0; q < 4; ++q) {
                float v = wv.x * (&c00.x)[q] + wv.y * (&c01.x)[q]
                        + wv.z * (&c10.x)[q] + wv.w * (&c11.x)[q];
                bf16 h = __float2bfloat16(v);
                hv[q] = h;
                lv[q] = __float2bfloat16(v - __bfloat162float(h));
            }
            *(uint2*)(ab + px * 48 + ciq * 8) = *(uint2*)hv;
            *(uint2*)(ab + 6144 + px * 48 + ciq * 8) = *(uint2*)lv;
        }
    };

    __syncthreads();       // params visible
    stage(0, 0, 0);
    __syncthreads();

    for (int s = 0; s < 72; ++s) {
        const int cur = s & 1;
        if (s + 1 < 72) stage((s + 1) / 9, (s + 1) % 9, cur ^ 1);

        uint32_t ah[2][4], al[2][4];
        #pragma unroll
        for (int m = 0; m < 2; ++m) {
            uint32_t aa = Asb + cur * 12288 + (uint32_t)(wm + m * 16 + (lane & 15)) * 48
                        + (lane >> 4) * 16;
            ldsm4(ah[m], aa);
            ldsm4(al[m], aa + 6144);
        }
        const uint32_t bq = Bsb + cur * 12288;
        const uint32_t boff = (uint32_t)((lane & 7) + ((lane >> 4) << 3)) * 48
                            + ((lane >> 3) & 1) * 16;
        uint32_t bb[4][4];
        #pragma unroll
        for (int nt = 0; nt < 4; ++nt)
            ldsm4(bb[nt], bq + (uint32_t)(wn + nt * 16) * 48 + boff);
        #pragma unroll
        for (int m = 0; m < 2; ++m)
            #pragma unroll
            for (int j = 0; j < 8; ++j) {
                uint32_t b0 = bb[j >> 1][(j & 1) * 2], b1 = bb[j >> 1][(j & 1) * 2 + 1];
                mma16816(d[m][j], ah[m], b0, b1);   // ah*bh
                mma16816(d[m][j], al[m], b0, b1);   // al*bh
            }
        #pragma unroll
        for (int nt = 0; nt < 4; ++nt)
            ldsm4(bb[nt], bq + 6144 + (uint32_t)(wn + nt * 16) * 48 + boff);
        #pragma unroll
        for (int m = 0; m < 2; ++m)
            #pragma unroll
            for (int j = 0; j < 8; ++j)
                mma16816(d[m][j], ah[m], bb[j >> 1][(j & 1) * 2], bb[j >> 1][(j & 1) * 2 + 1]); // ah*bl
        __syncthreads();
    }

    // epilogue: NCHW fp32 to d_out
    const int g = lane >> 2, tig = lane & 3;
    #pragma unroll
    for (int m = 0; m < 2; ++m) {
        #pragma unroll
        for (int j = 0; j < 8; ++j) {
            int col = wn + j * 8 + 2 * tig;
            float blo = s_bias[col], bhi = s_bias[col + 1];
            #pragma unroll
            for (int hrow = 0; hrow < 2; ++hrow) {
                int px = wm + m * 16 + g + hrow * 8;
                float v0 = d[m][j][hrow * 2] + blo;
                float v1 = d[m][j][hrow * 2 + 1] + bhi;
                float* o = out + (((size_t)(b * 128 + col) * HH + y0) * WW + px);
                o[0] = v0;
                o[HWSZ] = v1;
            }
        }
    }
}

// ---------------- launcher ----------------
extern "C" void kernel_launch(void* const* d_in, const int* in_sizes, int n_in,
                              void* d_out, int out_size) {
    const float* x    = (const float*)d_in[0];
    const float* cond = (const float*)d_in[1];
    const float* flow = (const float*)d_in[2];
    const float* w1 = (const float*)d_in[3];
    const float* b1 = (const float*)d_in[4];
    const float* w2 = (const float*)d_in[5];
    const float* b2 = (const float*)d_in[6];
    const float* w3 = (const float*)d_in[7];
    const float* b3 = (const float*)d_in[8];
    const float* w4 = (const float*)d_in[9];
    const float* b4 = (const float*)d_in[10];
    const float* wd = (const float*)d_in[11];
    const float* bd = (const float*)d_in[12];
    float* out = (float*)d_out;

    float *xtp, *headp, *b4p;
    bf16 *chp, *clp, *ahp, *alp, *bhp, *blp, *wt1, *wt2, *wt3, *wt4, *wtd;
    cudaGetSymbolAddress((void**)&xtp, g_xt);
    cudaGetSymbolAddress((void**)&chp, g_ch);
    cudaGetSymbolAddress((void**)&clp, g_cl);
    cudaGetSymbolAddress((void**)&ahp, g_ah);
    cudaGetSymbolAddress((void**)&alp, g_al);
    cudaGetSymbolAddress((void**)&bhp, g_bh);
    cudaGetSymbolAddress((void**)&blp, g_bl);
    cudaGetSymbolAddress((void**)&headp, g_head);
    cudaGetSymbolAddress((void**)&wt1, g_wt1);
    cudaGetSymbolAddress((void**)&wt2, g_wt2);
    cudaGetSymbolAddress((void**)&wt3, g_wt3);
    cudaGetSymbolAddress((void**)&wt4, g_wt4);
    cudaGetSymbolAddress((void**)&wtd, g_wtd);
    cudaGetSymbolAddress((void**)&b4p, g_b4p);

    const int SM128 = 2 * (3 * 132 * 48) + 2 * 2 * 128 * 48;   // 62592
    const int SM32  = 2 * (3 * 132 * 48) + 2 * 2 * 32 * 48;    // 44160
    cudaFuncSetAttribute(conv_mma<128, 18, C1P, 0>, cudaFuncAttributeMaxDynamicSharedMemorySize, SM128);
    cudaFuncSetAttribute(conv_mma<128, 8, 128, 0>,  cudaFuncAttributeMaxDynamicSharedMemorySize, SM128);
    cudaFuncSetAttribute(conv_mma<32, 8, 128, 1>,   cudaFuncAttributeMaxDynamicSharedMemorySize, SM32);
    cudaFuncSetAttribute(deform_mma, cudaFuncAttributeMaxDynamicSharedMemorySize, DM_SMEM);

    prep_kernel<<<PREP_NB, 256>>>(x, cond, w1, w2, w3, w4, wd, b4);

    dim3 gc(128, BB);
    conv_mma<128, 18, C1P, 0><<<gc, 256, SM128>>>(chp, clp, wt1, b1, ahp, alp, nullptr);
    conv_mma<128, 8, 128, 0><<<gc, 256, SM128>>>(ahp, alp, wt2, b2, bhp, blp, nullptr);
    conv_mma<128, 8, 128, 0><<<gc, 256, SM128>>>(bhp, blp, wt3, b3, ahp, alp, nullptr);
    conv_mma<32, 8, 128, 1><<<gc, 256, SM32>>>(ahp, alp, wt4, b4p, nullptr, nullptr, headp);

    deform_mma<<<gc, 256, DM_SMEM>>>(xtp, headp, flow, wtd, bd, out);
}